// round 13
// baseline (speedup 1.0000x reference)
#include <cuda_runtime.h>
#include <cuda_bf16.h>
#include <math.h>
#include <stdint.h>

#define Bq  2
#define Sq  2048
#define Dq  1024
#define Hq  16
#define DKq 64
#define Mq  (Bq*Sq)   // 4096

// activation hi/lo: 3 slots (q,k,v inputs); slot 0 reused for attention output
__device__ __nv_bfloat16 g_actH[(size_t)3*Mq*Dq];
__device__ __nv_bfloat16 g_actL[(size_t)3*Mq*Dq];
// weight hi/lo: 4 slots (wq,wk,wv,wo)
__device__ __nv_bfloat16 g_wH[(size_t)4*Dq*Dq];
__device__ __nv_bfloat16 g_wL[(size_t)4*Dq*Dq];
// head-major [b*16+h][s][64] bf16 (attention operands)
__device__ __nv_bfloat16 g_Qh[(size_t)Mq*Dq];
__device__ __nv_bfloat16 g_Ql[(size_t)Mq*Dq];
__device__ __nv_bfloat16 g_Kh[(size_t)Mq*Dq];
__device__ __nv_bfloat16 g_Kl[(size_t)Mq*Dq];
__device__ __nv_bfloat16 g_Vh[(size_t)Mq*Dq];
__device__ __nv_bfloat16 g_Vl[(size_t)Mq*Dq];
// split-K partial for the out-projection
__device__ float g_scr[(size_t)Mq*Dq];

// ---------------------------------------------------------------------------
// helpers
// ---------------------------------------------------------------------------
__device__ __forceinline__ uint32_t smem_u32(const void* p) {
    uint32_t a;
    asm("{ .reg .u64 t; cvta.to.shared.u64 t, %1; cvt.u32.u64 %0, t; }" : "=r"(a) : "l"(p));
    return a;
}
__device__ __forceinline__ void cpa16(uint32_t saddr, const void* g) {
    asm volatile("cp.async.ca.shared.global [%0], [%1], 16;" :: "r"(saddr), "l"(g));
}
__device__ __forceinline__ void ldsm4(uint32_t* r, uint32_t addr) {
    asm volatile("ldmatrix.sync.aligned.m8n8.x4.shared.b16 {%0,%1,%2,%3}, [%4];"
        : "=r"(r[0]), "=r"(r[1]), "=r"(r[2]), "=r"(r[3]) : "r"(addr));
}
__device__ __forceinline__ void ldsm4t(uint32_t* r, uint32_t addr) {
    asm volatile("ldmatrix.sync.aligned.m8n8.x4.trans.shared.b16 {%0,%1,%2,%3}, [%4];"
        : "=r"(r[0]), "=r"(r[1]), "=r"(r[2]), "=r"(r[3]) : "r"(addr));
}
__device__ __forceinline__ void mma_bf16(float* c, const uint32_t* a, const uint32_t* b) {
    asm volatile("mma.sync.aligned.m16n8k16.row.col.f32.bf16.bf16.f32 "
        "{%0,%1,%2,%3}, {%4,%5,%6,%7}, {%8,%9}, {%0,%1,%2,%3};"
        : "+f"(c[0]), "+f"(c[1]), "+f"(c[2]), "+f"(c[3])
        : "r"(a[0]), "r"(a[1]), "r"(a[2]), "r"(a[3]), "r"(b[0]), "r"(b[1]));
}
__device__ __forceinline__ uint32_t pack_bf2(float lo, float hi) {
    __nv_bfloat162 t = __floats2bfloat162_rn(lo, hi);
    return *(uint32_t*)&t;
}
__device__ __forceinline__ void store_hilo(__nv_bfloat16* H, __nv_bfloat16* L,
                                           size_t o, float x, float y) {
    __nv_bfloat16 hx = __float2bfloat16(x);
    __nv_bfloat16 hy = __float2bfloat16(y);
    *(__nv_bfloat162*)(H + o) = __nv_bfloat162(hx, hy);
    *(__nv_bfloat162*)(L + o) = __nv_bfloat162(
        __float2bfloat16(x - __bfloat162float(hx)),
        __float2bfloat16(y - __bfloat162float(hy)));
}

// ---------------------------------------------------------------------------
// fp32 -> bf16 hi/lo split; grid.y selects one of up-to-4 tensors.
// ---------------------------------------------------------------------------
__global__ __launch_bounds__(256) void split_multi(
    const float* __restrict__ x0, const float* __restrict__ x1,
    const float* __restrict__ x2, const float* __restrict__ x3,
    __nv_bfloat16* __restrict__ h, __nv_bfloat16* __restrict__ l, int n4)
{
    const float* srcs[4] = { x0, x1, x2, x3 };
    const float* x = srcs[blockIdx.y];
    size_t slot = (size_t)blockIdx.y * 2u * (size_t)n4;
    int i = blockIdx.x * blockDim.x + threadIdx.x;
    if (i >= n4) return;
    float4 v = ((const float4*)x)[i];
    __nv_bfloat16 h0 = __float2bfloat16(v.x), h1 = __float2bfloat16(v.y);
    __nv_bfloat16 h2 = __float2bfloat16(v.z), h3 = __float2bfloat16(v.w);
    __nv_bfloat16 l0 = __float2bfloat16(v.x - __bfloat162float(h0));
    __nv_bfloat16 l1 = __float2bfloat16(v.y - __bfloat162float(h1));
    __nv_bfloat16 l2 = __float2bfloat16(v.z - __bfloat162float(h2));
    __nv_bfloat16 l3 = __float2bfloat16(v.w - __bfloat162float(h3));
    ((__nv_bfloat162*)h)[slot + 2*i]   = __nv_bfloat162(h0, h1);
    ((__nv_bfloat162*)h)[slot + 2*i+1] = __nv_bfloat162(h2, h3);
    ((__nv_bfloat162*)l)[slot + 2*i]   = __nv_bfloat162(l0, l1);
    ((__nv_bfloat162*)l)[slot + 2*i+1] = __nv_bfloat162(l2, l3);
}

// ---------------------------------------------------------------------------
// GEMM mainloop. Kloop = summed K extent; Kst = row stride in elements.
// 128x128 CTA tile, 4 warps (64x64), K-chunk 32, 3-stage cp.async pipeline.
// ---------------------------------------------------------------------------
#define TILE8K 8192
#define STAGE_B 32768
__device__ __forceinline__ void gemm_mainloop(
    const __nv_bfloat16* const* srcs, uint32_t sbase, int tid,
    int wm, int wn, int lane, int Kloop, int Kst, float acc[4][8][4])
{
    const int nkc = Kloop >> 5;
    const int lt  = lane >> 3;
    const int lr8 = lane & 7;

    #pragma unroll
    for (int st = 0; st < 2; st++) {
        const int kofs = st << 5;
        const uint32_t stb = sbase + st * STAGE_B;
        #pragma unroll
        for (int t = 0; t < 4; t++) {
            const char* s = (const char*)(srcs[t] + kofs);
            uint32_t db = stb + t * TILE8K;
            #pragma unroll
            for (int j = 0; j < 4; j++) {
                int idx = tid + j*128;
                int r = idx >> 2, c = idx & 3;
                cpa16(db + r*64 + ((c ^ ((r>>1)&3))<<4), s + (size_t)r*(Kst*2) + c*16);
            }
        }
        asm volatile("cp.async.commit_group;");
    }

    int buf = 0;
    for (int kc = 0; kc < nkc; kc++) {
        if (kc + 1 < nkc) asm volatile("cp.async.wait_group 1;");
        else              asm volatile("cp.async.wait_group 0;");
        __syncthreads();

        if (kc + 2 < nkc) {
            const int kofs = (kc + 2) << 5;
            int nb3 = buf + 2; if (nb3 >= 3) nb3 -= 3;
            const uint32_t stb = sbase + nb3 * STAGE_B;
            #pragma unroll
            for (int t = 0; t < 4; t++) {
                const char* s = (const char*)(srcs[t] + kofs);
                uint32_t db = stb + t * TILE8K;
                #pragma unroll
                for (int j = 0; j < 4; j++) {
                    int idx = tid + j*128;
                    int r = idx >> 2, c = idx & 3;
                    cpa16(db + r*64 + ((c ^ ((r>>1)&3))<<4), s + (size_t)r*(Kst*2) + c*16);
                }
            }
            asm volatile("cp.async.commit_group;");
        }

        const uint32_t abH = sbase + buf * STAGE_B;
        const uint32_t abL = abH + TILE8K;
        const uint32_t wbH = abH + 2 * TILE8K;
        const uint32_t wbL = abH + 3 * TILE8K;

        #pragma unroll
        for (int ka = 0; ka < 2; ka++) {
            uint32_t aH[4][4], aL[4][4], bH[8][2], bL[8][2];
            #pragma unroll
            for (int ma = 0; ma < 4; ma++) {
                int row = wm + ma*16 + ((lt & 1) << 3) + lr8;
                int ch  = (ka << 1) + (lt >> 1);
                uint32_t off = (uint32_t)(row*64 + ((ch ^ ((row>>1)&3)) << 4));
                ldsm4(aH[ma], abH + off);
                ldsm4(aL[ma], abL + off);
            }
            #pragma unroll
            for (int nb = 0; nb < 4; nb++) {
                int row = wn + nb*16 + ((lt >> 1) << 3) + lr8;
                int ch  = (ka << 1) + (lt & 1);
                uint32_t off = (uint32_t)(row*64 + ((ch ^ ((row>>1)&3)) << 4));
                uint32_t r[4];
                ldsm4(r, wbH + off);
                bH[2*nb][0]=r[0]; bH[2*nb][1]=r[1]; bH[2*nb+1][0]=r[2]; bH[2*nb+1][1]=r[3];
                ldsm4(r, wbL + off);
                bL[2*nb][0]=r[0]; bL[2*nb][1]=r[1]; bL[2*nb+1][0]=r[2]; bL[2*nb+1][1]=r[3];
            }
            #pragma unroll
            for (int ma = 0; ma < 4; ma++)
                #pragma unroll
                for (int na = 0; na < 8; na++)
                    mma_bf16(acc[ma][na], aH[ma], bH[na]);
            #pragma unroll
            for (int ma = 0; ma < 4; ma++)
                #pragma unroll
                for (int na = 0; na < 8; na++)
                    mma_bf16(acc[ma][na], aL[ma], bH[na]);
            #pragma unroll
            for (int ma = 0; ma < 4; ma++)
                #pragma unroll
                for (int na = 0; na < 8; na++)
                    mma_bf16(acc[ma][na], aH[ma], bL[na]);
        }
        buf++; if (buf >= 3) buf = 0;
    }
}

// ---------------------------------------------------------------------------
// Out-projection GEMM, split-K x2: blockIdx.z selects K half and output
// buffer (z=0 -> C0, z=1 -> C1). No bias (applied in add_bias).
// ---------------------------------------------------------------------------
__global__ __launch_bounds__(128) void gemm_splitk(
    const __nv_bfloat16* __restrict__ Ah, const __nv_bfloat16* __restrict__ Al,
    const __nv_bfloat16* __restrict__ Wh, const __nv_bfloat16* __restrict__ Wl,
    float* __restrict__ C0, float* __restrict__ C1, int M, int N, int K)
{
    extern __shared__ __align__(1024) char sm[];
    const uint32_t sbase = smem_u32(sm);
    const int tid = threadIdx.x;
    const int wid = tid >> 5, lane = tid & 31;
    const int bm = blockIdx.y * 128, bn = blockIdx.x * 128;
    const int wm = (wid >> 1) * 64, wn = (wid & 1) * 64;
    const int z = blockIdx.z;
    const int kh = K >> 1;
    const int kbase = z * kh;
    float* C = z ? C1 : C0;

    const __nv_bfloat16* srcs[4] = {
        Ah + (size_t)bm * K + kbase, Al + (size_t)bm * K + kbase,
        Wh + (size_t)bn * K + kbase, Wl + (size_t)bn * K + kbase };

    float acc[4][8][4] = {};
    gemm_mainloop(srcs, sbase, tid, wm, wn, lane, kh, K, acc);

    #pragma unroll
    for (int ma = 0; ma < 4; ma++) {
        int r = bm + wm + ma*16 + (lane >> 2);
        #pragma unroll
        for (int na = 0; na < 8; na++) {
            int col = bn + wn + na*8 + (lane & 3)*2;
            float2 v0 = { acc[ma][na][0], acc[ma][na][1] };
            float2 v1 = { acc[ma][na][2], acc[ma][na][3] };
            *(float2*)(C + (size_t)r * N + col)       = v0;
            *(float2*)(C + (size_t)(r + 8) * N + col) = v1;
        }
    }
}

// out = C0 + C1 + bias  (row-broadcast bias, 1024 cols)
__global__ __launch_bounds__(256) void add_bias(
    float* __restrict__ out, const float* __restrict__ scr,
    const float* __restrict__ bias)
{
    int i = blockIdx.x * blockDim.x + threadIdx.x;   // float4 index
    float4 a = ((const float4*)out)[i];
    float4 b = ((const float4*)scr)[i];
    float4 c = ((const float4*)bias)[i & 255];
    float4 r = { a.x + b.x + c.x, a.y + b.y + c.y,
                 a.z + b.z + c.z, a.w + b.w + c.w };
    ((float4*)out)[i] = r;
}

// ---------------------------------------------------------------------------
// Fused QKV GEMM: blockIdx.z = 0(Q)/1(K)/2(V). Epilogue applies bias, then
// Q/K: RMSNorm(DK=64) + RoPE;  V: passthrough. Writes bf16 hi/lo head-major.
// ---------------------------------------------------------------------------
__global__ __launch_bounds__(128) void gemm_qkv(
    const __nv_bfloat16* __restrict__ Ah, const __nv_bfloat16* __restrict__ Al,
    const __nv_bfloat16* __restrict__ Wh, const __nv_bfloat16* __restrict__ Wl,
    size_t strideA, size_t strideW,
    const float* __restrict__ bq, const float* __restrict__ bk,
    const float* __restrict__ bv,
    const float* __restrict__ qn, const float* __restrict__ kn,
    const float* __restrict__ cs, const float* __restrict__ sn,
    __nv_bfloat16* __restrict__ Qh, __nv_bfloat16* __restrict__ Ql,
    __nv_bfloat16* __restrict__ Kh, __nv_bfloat16* __restrict__ Kl,
    __nv_bfloat16* __restrict__ Vh, __nv_bfloat16* __restrict__ Vl,
    int M, int N, int K)
{
    extern __shared__ __align__(1024) char sm[];
    const uint32_t sbase = smem_u32(sm);
    const int tid = threadIdx.x;
    const int wid = tid >> 5, lane = tid & 31;
    const int bm = blockIdx.y * 128, bn = blockIdx.x * 128;
    const int wm = (wid >> 1) * 64, wn = (wid & 1) * 64;
    const int z = blockIdx.z;
    const size_t zA = (size_t)z * strideA, zW = (size_t)z * strideW;

    const __nv_bfloat16* srcs[4] = {
        Ah + zA + (size_t)bm * K, Al + zA + (size_t)bm * K,
        Wh + zW + (size_t)bn * K, Wl + zW + (size_t)bn * K };

    float acc[4][8][4] = {};
    gemm_mainloop(srcs, sbase, tid, wm, wn, lane, K, K, acc);

    const float* bias = (z == 0) ? bq : (z == 1) ? bk : bv;
    __nv_bfloat16* OH = (z == 0) ? Qh : (z == 1) ? Kh : Vh;
    __nv_bfloat16* OL = (z == 0) ? Ql : (z == 1) ? Kl : Vl;

    const int lg = lane >> 2, tg = lane & 3;
    const int h = (bn + wn) >> 6;

    float2 bb[8];
    #pragma unroll
    for (int na = 0; na < 8; na++)
        bb[na] = *(const float2*)(bias + bn + wn + na*8 + tg*2);

    float wt[8][2];
    if (z < 2) {
        const float* w = (z == 0) ? qn : kn;
        #pragma unroll
        for (int na = 0; na < 8; na++) {
            float2 w2 = *(const float2*)(w + na*8 + tg*2);
            wt[na][0] = w2.x; wt[na][1] = w2.y;
        }
    }

    #pragma unroll
    for (int ma = 0; ma < 4; ma++) {
        #pragma unroll
        for (int half = 0; half < 2; half++) {
            int r = bm + wm + ma*16 + lg + half*8;
            int b = r >> 11, s = r & (Sq - 1);
            size_t ob = (((size_t)(b*16 + h))*Sq + s)*64;

            float v[8][2];
            float ss = 0.f;
            #pragma unroll
            for (int na = 0; na < 8; na++) {
                v[na][0] = acc[ma][na][2*half]   + bb[na].x;
                v[na][1] = acc[ma][na][2*half+1] + bb[na].y;
                ss += v[na][0]*v[na][0] + v[na][1]*v[na][1];
            }

            if (z == 2) {
                #pragma unroll
                for (int na = 0; na < 8; na++)
                    store_hilo(OH, OL, ob + na*8 + tg*2, v[na][0], v[na][1]);
            } else {
                ss += __shfl_xor_sync(0xffffffffu, ss, 1);
                ss += __shfl_xor_sync(0xffffffffu, ss, 2);
                float inv = rsqrtf(ss*(1.0f/64.0f) + 1e-6f);
                const float* crow = cs + (size_t)s*64;
                const float* srow = sn + (size_t)s*64;
                #pragma unroll
                for (int na = 0; na < 4; na++) {
                    int d = na*8 + tg*2;
                    float y0a = v[na][0]*inv*wt[na][0];
                    float y0b = v[na][1]*inv*wt[na][1];
                    float y1a = v[na+4][0]*inv*wt[na+4][0];
                    float y1b = v[na+4][1]*inv*wt[na+4][1];
                    float2 c0 = *(const float2*)(crow + d);
                    float2 s0 = *(const float2*)(srow + d);
                    float2 c1 = *(const float2*)(crow + d + 32);
                    float2 s1 = *(const float2*)(srow + d + 32);
                    float o0a = y0a*c0.x - y1a*s0.x;
                    float o0b = y0b*c0.y - y1b*s0.y;
                    float o1a = y1a*c1.x + y0a*s1.x;
                    float o1b = y1b*c1.y + y0b*s1.y;
                    store_hilo(OH, OL, ob + d,      o0a, o0b);
                    store_hilo(OH, OL, ob + d + 32, o1a, o1b);
                }
            }
        }
    }
}

// ---------------------------------------------------------------------------
// Flash attention, causal, bf16 mma.sync with hi/lo compensation.
// Fixed-max softmax (post-RMSNorm bound: S in [-8,8]); no running max.
// ---------------------------------------------------------------------------
#define ATT_SMEM (32768 + 2*32768)
__global__ __launch_bounds__(256, 2) void flash_attn_tc(
    const __nv_bfloat16* __restrict__ Qh, const __nv_bfloat16* __restrict__ Ql,
    const __nv_bfloat16* __restrict__ Kh, const __nv_bfloat16* __restrict__ Kl,
    const __nv_bfloat16* __restrict__ Vh, const __nv_bfloat16* __restrict__ Vl,
    __nv_bfloat16* __restrict__ Oh, __nv_bfloat16* __restrict__ Ol)
{
    extern __shared__ __align__(1024) char sm[];
    const uint32_t sQ = smem_u32(sm);
    const uint32_t sStage = sQ + 32768;
    const int tid = threadIdx.x, wid = tid >> 5, lane = tid & 31;
    const int qb = gridDim.x - 1 - blockIdx.x;
    const int bh = blockIdx.y;
    const int q0 = qb * 128;
    const size_t hb = (size_t)bh * Sq * DKq;

    const char* gQh = (const char*)(Qh + hb + (size_t)q0*64);
    const char* gQl = (const char*)(Ql + hb + (size_t)q0*64);
    const char* gKh = (const char*)(Kh + hb);
    const char* gKl = (const char*)(Kl + hb);
    const char* gVh = (const char*)(Vh + hb);
    const char* gVl = (const char*)(Vl + hb);

    const int nkb = 2*qb + 2;

    #pragma unroll
    for (int j = 0; j < 4; j++) {
        int i = tid + j*256;
        int r = i >> 3, c = i & 7;
        uint32_t so = (uint32_t)(r*128 + ((c ^ (r&7)) << 4));
        cpa16(sQ + so,         gQh + r*128 + c*16);
        cpa16(sQ + 16384 + so, gQl + r*128 + c*16);
    }
    {
        const char* gs[4] = { gKh, gKl, gVh, gVl };
        #pragma unroll
        for (int t = 0; t < 4; t++)
            #pragma unroll
            for (int j = 0; j < 2; j++) {
                int i = tid + j*256;
                int r = i >> 3, c = i & 7;
                uint32_t so = (uint32_t)(r*128 + ((c ^ (r&7)) << 4));
                cpa16(sStage + t*8192 + so, gs[t] + r*128 + c*16);
            }
    }
    asm volatile("cp.async.commit_group;");

    float o[8][4] = {};
    float S[8][4];
    float l0 = 0.f, l1 = 0.f;
    uint32_t qfh[4][4];

    const int lg = lane >> 2;
    const int tg = lane & 3;
    const int lrow = (((lane >> 3) & 1) << 3) + (lane & 7);
    const int lsel = lane >> 4;

    const float c1 = 0.125f * 1.4426950408889634f;
    const float c2 = 8.0f  * 1.4426950408889634f;

    for (int kb = 0; kb < nkb; kb++) {
        if (kb + 1 < nkb) {
            const uint32_t stb = sStage + ((kb+1) & 1) * 32768;
            const int kvr = (kb+1) * 64;
            const char* gs[4] = { gKh, gKl, gVh, gVl };
            #pragma unroll
            for (int t = 0; t < 4; t++)
                #pragma unroll
                for (int j = 0; j < 2; j++) {
                    int i = tid + j*256;
                    int r = i >> 3, c = i & 7;
                    uint32_t so = (uint32_t)(r*128 + ((c ^ (r&7)) << 4));
                    cpa16(stb + t*8192 + so, gs[t] + (size_t)(kvr + r)*128 + c*16);
                }
            asm volatile("cp.async.commit_group;");
            asm volatile("cp.async.wait_group 1;");
        } else {
            asm volatile("cp.async.wait_group 0;");
        }
        __syncthreads();

        if (kb == 0) {
            #pragma unroll
            for (int ka = 0; ka < 4; ka++) {
                int r = wid*16 + lrow;
                int c = 2*ka + lsel;
                ldsm4(qfh[ka], sQ + (uint32_t)(r*128 + ((c ^ (r&7)) << 4)));
            }
        }

        const bool active = (kb*64 <= q0 + wid*16 + 15);
        if (active) {
            const uint32_t bK = sStage + (kb & 1) * 32768;
            #pragma unroll
            for (int n = 0; n < 8; n++)
                #pragma unroll
                for (int x = 0; x < 4; x++) S[n][x] = 0.f;

            #pragma unroll
            for (int ka = 0; ka < 4; ka++) {
                uint32_t qlw[4];
                {
                    int r = wid*16 + lrow;
                    int c = 2*ka + lsel;
                    ldsm4(qlw, sQ + 16384 + (uint32_t)(r*128 + ((c ^ (r&7)) << 4)));
                }
                #pragma unroll
                for (int n16 = 0; n16 < 4; n16++) {
                    int r = n16*16 + lrow;
                    int c = 2*ka + lsel;
                    uint32_t off = (uint32_t)(r*128 + ((c ^ (r&7)) << 4));
                    uint32_t kh4[4], kl4[4];
                    ldsm4(kh4, bK + off);
                    ldsm4(kl4, bK + 8192 + off);
                    uint32_t bh0[2] = { kh4[0], kh4[2] }, bh1[2] = { kh4[1], kh4[3] };
                    uint32_t bl0[2] = { kl4[0], kl4[2] }, bl1[2] = { kl4[1], kl4[3] };
                    mma_bf16(S[2*n16],   qfh[ka], bh0);
                    mma_bf16(S[2*n16],   qlw,     bh0);
                    mma_bf16(S[2*n16],   qfh[ka], bl0);
                    mma_bf16(S[2*n16+1], qfh[ka], bh1);
                    mma_bf16(S[2*n16+1], qlw,     bh1);
                    mma_bf16(S[2*n16+1], qfh[ka], bl1);
                }
            }

            const int row0 = q0 + wid*16 + lg;
            const int row1 = row0 + 8;
            float sum0 = 0.f, sum1 = 0.f;
            if (kb >= 2*qb) {
                #pragma unroll
                for (int n = 0; n < 8; n++) {
                    int col0 = kb*64 + n*8 + tg*2;
                    float e0 = exp2f(fmaf(S[n][0], c1, -c2));
                    float e1 = exp2f(fmaf(S[n][1], c1, -c2));
                    float e2 = exp2f(fmaf(S[n][2], c1, -c2));
                    float e3 = exp2f(fmaf(S[n][3], c1, -c2));
                    if (col0     > row0) e0 = 0.f;
                    if (col0 + 1 > row0) e1 = 0.f;
                    if (col0     > row1) e2 = 0.f;
                    if (col0 + 1 > row1) e3 = 0.f;
                    S[n][0] = e0; S[n][1] = e1; S[n][2] = e2; S[n][3] = e3;
                    sum0 += e0 + e1;
                    sum1 += e2 + e3;
                }
            } else {
                #pragma unroll
                for (int n = 0; n < 8; n++) {
                    float e0 = exp2f(fmaf(S[n][0], c1, -c2));
                    float e1 = exp2f(fmaf(S[n][1], c1, -c2));
                    float e2 = exp2f(fmaf(S[n][2], c1, -c2));
                    float e3 = exp2f(fmaf(S[n][3], c1, -c2));
                    S[n][0] = e0; S[n][1] = e1; S[n][2] = e2; S[n][3] = e3;
                    sum0 += e0 + e1;
                    sum1 += e2 + e3;
                }
            }
            sum0 += __shfl_xor_sync(0xffffffffu, sum0, 1);
            sum0 += __shfl_xor_sync(0xffffffffu, sum0, 2);
            sum1 += __shfl_xor_sync(0xffffffffu, sum1, 1);
            sum1 += __shfl_xor_sync(0xffffffffu, sum1, 2);
            l0 += sum0;
            l1 += sum1;

            const uint32_t bV = bK + 16384;
            #pragma unroll
            for (int ka = 0; ka < 4; ka++) {
                uint32_t ah[4], al[4];
                #pragma unroll
                for (int half = 0; half < 2; half++) {
                    const float* s4 = S[2*ka + half];
                    __nv_bfloat162 h01 = __floats2bfloat162_rn(s4[0], s4[1]);
                    __nv_bfloat162 h23 = __floats2bfloat162_rn(s4[2], s4[3]);
                    float2 f01 = __bfloat1622float2(h01);
                    float2 f23 = __bfloat1622float2(h23);
                    ah[2*half+0] = *(uint32_t*)&h01;
                    ah[2*half+1] = *(uint32_t*)&h23;
                    al[2*half+0] = pack_bf2(s4[0] - f01.x, s4[1] - f01.y);
                    al[2*half+1] = pack_bf2(s4[2] - f23.x, s4[3] - f23.y);
                }
                #pragma unroll
                for (int ndp = 0; ndp < 4; ndp++) {
                    int r = ka*16 + lrow;
                    int c = 2*ndp + lsel;
                    uint32_t off = (uint32_t)(r*128 + ((c ^ (r&7)) << 4));
                    uint32_t vh4[4], vl4[4];
                    ldsm4t(vh4, bV + off);
                    ldsm4t(vl4, bV + 8192 + off);
                    uint32_t bh0[2] = { vh4[0], vh4[1] }, bh1[2] = { vh4[2], vh4[3] };
                    uint32_t bl0[2] = { vl4[0], vl4[1] }, bl1[2] = { vl4[2], vl4[3] };
                    mma_bf16(o[2*ndp],   ah, bh0);
                    mma_bf16(o[2*ndp],   al, bh0);
                    mma_bf16(o[2*ndp],   ah, bl0);
                    mma_bf16(o[2*ndp+1], ah, bh1);
                    mma_bf16(o[2*ndp+1], al, bh1);
                    mma_bf16(o[2*ndp+1], ah, bl1);
                }
            }
        }
        __syncthreads();
    }

    const float inv0 = 1.0f / l0, inv1 = 1.0f / l1;
    const int b = bh >> 4, h = bh & 15;
    const int r0g = b*Sq + q0 + wid*16 + lg;
    size_t base0 = (size_t)r0g * Dq + h*64 + tg*2;
    size_t base1 = base0 + (size_t)8 * Dq;
    #pragma unroll
    for (int n = 0; n < 8; n++) {
        store_hilo(Oh, Ol, base0 + n*8, o[n][0]*inv0, o[n][1]*inv0);
        store_hilo(Oh, Ol, base1 + n*8, o[n][2]*inv1, o[n][3]*inv1);
    }
}

// ---------------------------------------------------------------------------
extern "C" void kernel_launch(void* const* d_in, const int* in_sizes, int n_in,
                              void* d_out, int out_size)
{
    (void)in_sizes; (void)n_in; (void)out_size;
    const float* q  = (const float*)d_in[0];
    const float* k  = (const float*)d_in[1];
    const float* v  = (const float*)d_in[2];
    const float* cs = (const float*)d_in[4];
    const float* sn = (const float*)d_in[5];
    const float* wq = (const float*)d_in[6];
    const float* bq = (const float*)d_in[7];
    const float* wk = (const float*)d_in[8];
    const float* bk = (const float*)d_in[9];
    const float* wv = (const float*)d_in[10];
    const float* bv = (const float*)d_in[11];
    const float* wo = (const float*)d_in[12];
    const float* bo = (const float*)d_in[13];
    const float* qn = (const float*)d_in[14];
    const float* kn = (const float*)d_in[15];
    float* out = (float*)d_out;

    __nv_bfloat16 *aH, *aL, *wH, *wL, *qh, *ql, *kh, *kl, *vh, *vl;
    float* scr;
    cudaGetSymbolAddress((void**)&aH, g_actH);
    cudaGetSymbolAddress((void**)&aL, g_actL);
    cudaGetSymbolAddress((void**)&wH, g_wH);
    cudaGetSymbolAddress((void**)&wL, g_wL);
    cudaGetSymbolAddress((void**)&qh, g_Qh);
    cudaGetSymbolAddress((void**)&ql, g_Ql);
    cudaGetSymbolAddress((void**)&kh, g_Kh);
    cudaGetSymbolAddress((void**)&kl, g_Kl);
    cudaGetSymbolAddress((void**)&vh, g_Vh);
    cudaGetSymbolAddress((void**)&vl, g_Vl);
    cudaGetSymbolAddress((void**)&scr, g_scr);

    const size_t actN = (size_t)Mq*Dq, wN = (size_t)Dq*Dq;
    const int actN4 = (int)(actN/4), wN4 = (int)(wN/4);
    const int gsm = 3 * STAGE_B;   // 98304
    cudaFuncSetAttribute(gemm_splitk, cudaFuncAttributeMaxDynamicSharedMemorySize, gsm);
    cudaFuncSetAttribute(gemm_qkv,    cudaFuncAttributeMaxDynamicSharedMemorySize, gsm);
    cudaFuncSetAttribute(flash_attn_tc, cudaFuncAttributeMaxDynamicSharedMemorySize, ATT_SMEM);

    split_multi<<<dim3(actN4/256, 3), 256>>>(q, k, v, v, aH, aL, actN4);
    split_multi<<<dim3(wN4/256, 4), 256>>>(wq, wk, wv, wo, wH, wL, wN4);

    gemm_qkv<<<dim3(Dq/128, Mq/128, 3), 128, gsm>>>(
        aH, aL, wH, wL, actN, wN, bq, bk, bv, qn, kn, cs, sn,
        qh, ql, kh, kl, vh, vl, Mq, Dq, Dq);

    flash_attn_tc<<<dim3(Sq/128, Bq*Hq), 256, ATT_SMEM>>>(qh, ql, kh, kl, vh, vl, aH, aL);

    // out-projection: split-K x2 (balanced 512 CTAs) + bias/reduce
    gemm_splitk<<<dim3(Dq/128, Mq/128, 2), 128, gsm>>>(
        aH, aL, wH + 3*wN, wL + 3*wN, out, scr, Mq, Dq, Dq);
    add_bias<<<Mq*Dq/4/256, 256>>>(out, scr, bo);
}

// round 14
// speedup vs baseline: 1.0758x; 1.0758x over previous
#include <cuda_runtime.h>
#include <cuda_bf16.h>
#include <math.h>
#include <stdint.h>

#define Bq  2
#define Sq  2048
#define Dq  1024
#define Hq  16
#define DKq 64
#define Mq  (Bq*Sq)   // 4096

// activation hi/lo: 3 slots (q,k,v inputs); slot 0 reused for attention output
__device__ __nv_bfloat16 g_actH[(size_t)3*Mq*Dq];
__device__ __nv_bfloat16 g_actL[(size_t)3*Mq*Dq];
// weight hi/lo: 4 slots (wq,wk,wv,wo)
__device__ __nv_bfloat16 g_wH[(size_t)4*Dq*Dq];
__device__ __nv_bfloat16 g_wL[(size_t)4*Dq*Dq];
// head-major [b*16+h][s][64] bf16 (attention operands)
__device__ __nv_bfloat16 g_Qh[(size_t)Mq*Dq];
__device__ __nv_bfloat16 g_Ql[(size_t)Mq*Dq];
__device__ __nv_bfloat16 g_Kh[(size_t)Mq*Dq];
__device__ __nv_bfloat16 g_Kl[(size_t)Mq*Dq];
__device__ __nv_bfloat16 g_Vh[(size_t)Mq*Dq];
__device__ __nv_bfloat16 g_Vl[(size_t)Mq*Dq];
// split-KV partial O (fp32, [bs][h*64+d]) and row sums l
__device__ float g_O0[(size_t)Mq*Dq];
__device__ float g_O1[(size_t)Mq*Dq];
__device__ float g_L0[(size_t)Bq*Hq*Sq];
__device__ float g_L1[(size_t)Bq*Hq*Sq];

// ---------------------------------------------------------------------------
// helpers
// ---------------------------------------------------------------------------
__device__ __forceinline__ uint32_t smem_u32(const void* p) {
    uint32_t a;
    asm("{ .reg .u64 t; cvta.to.shared.u64 t, %1; cvt.u32.u64 %0, t; }" : "=r"(a) : "l"(p));
    return a;
}
__device__ __forceinline__ void cpa16(uint32_t saddr, const void* g) {
    asm volatile("cp.async.ca.shared.global [%0], [%1], 16;" :: "r"(saddr), "l"(g));
}
__device__ __forceinline__ void ldsm4(uint32_t* r, uint32_t addr) {
    asm volatile("ldmatrix.sync.aligned.m8n8.x4.shared.b16 {%0,%1,%2,%3}, [%4];"
        : "=r"(r[0]), "=r"(r[1]), "=r"(r[2]), "=r"(r[3]) : "r"(addr));
}
__device__ __forceinline__ void ldsm4t(uint32_t* r, uint32_t addr) {
    asm volatile("ldmatrix.sync.aligned.m8n8.x4.trans.shared.b16 {%0,%1,%2,%3}, [%4];"
        : "=r"(r[0]), "=r"(r[1]), "=r"(r[2]), "=r"(r[3]) : "r"(addr));
}
__device__ __forceinline__ void mma_bf16(float* c, const uint32_t* a, const uint32_t* b) {
    asm volatile("mma.sync.aligned.m16n8k16.row.col.f32.bf16.bf16.f32 "
        "{%0,%1,%2,%3}, {%4,%5,%6,%7}, {%8,%9}, {%0,%1,%2,%3};"
        : "+f"(c[0]), "+f"(c[1]), "+f"(c[2]), "+f"(c[3])
        : "r"(a[0]), "r"(a[1]), "r"(a[2]), "r"(a[3]), "r"(b[0]), "r"(b[1]));
}
__device__ __forceinline__ uint32_t pack_bf2(float lo, float hi) {
    __nv_bfloat162 t = __floats2bfloat162_rn(lo, hi);
    return *(uint32_t*)&t;
}
__device__ __forceinline__ void store_hilo(__nv_bfloat16* H, __nv_bfloat16* L,
                                           size_t o, float x, float y) {
    __nv_bfloat16 hx = __float2bfloat16(x);
    __nv_bfloat16 hy = __float2bfloat16(y);
    *(__nv_bfloat162*)(H + o) = __nv_bfloat162(hx, hy);
    *(__nv_bfloat162*)(L + o) = __nv_bfloat162(
        __float2bfloat16(x - __bfloat162float(hx)),
        __float2bfloat16(y - __bfloat162float(hy)));
}

// ---------------------------------------------------------------------------
// fp32 -> bf16 hi/lo split; grid.y selects one of up-to-4 tensors.
// ---------------------------------------------------------------------------
__global__ __launch_bounds__(256) void split_multi(
    const float* __restrict__ x0, const float* __restrict__ x1,
    const float* __restrict__ x2, const float* __restrict__ x3,
    __nv_bfloat16* __restrict__ h, __nv_bfloat16* __restrict__ l, int n4)
{
    const float* srcs[4] = { x0, x1, x2, x3 };
    const float* x = srcs[blockIdx.y];
    size_t slot = (size_t)blockIdx.y * 2u * (size_t)n4;
    int i = blockIdx.x * blockDim.x + threadIdx.x;
    if (i >= n4) return;
    float4 v = ((const float4*)x)[i];
    __nv_bfloat16 h0 = __float2bfloat16(v.x), h1 = __float2bfloat16(v.y);
    __nv_bfloat16 h2 = __float2bfloat16(v.z), h3 = __float2bfloat16(v.w);
    __nv_bfloat16 l0 = __float2bfloat16(v.x - __bfloat162float(h0));
    __nv_bfloat16 l1 = __float2bfloat16(v.y - __bfloat162float(h1));
    __nv_bfloat16 l2 = __float2bfloat16(v.z - __bfloat162float(h2));
    __nv_bfloat16 l3 = __float2bfloat16(v.w - __bfloat162float(h3));
    ((__nv_bfloat162*)h)[slot + 2*i]   = __nv_bfloat162(h0, h1);
    ((__nv_bfloat162*)h)[slot + 2*i+1] = __nv_bfloat162(h2, h3);
    ((__nv_bfloat162*)l)[slot + 2*i]   = __nv_bfloat162(l0, l1);
    ((__nv_bfloat162*)l)[slot + 2*i+1] = __nv_bfloat162(l2, l3);
}

// ---------------------------------------------------------------------------
// GEMM mainloop. 128x128 CTA tile, 4 warps (64x64), K-chunk 32,
// 3-stage cp.async pipeline, one syncthreads per K-iter.
// ---------------------------------------------------------------------------
#define TILE8K 8192
#define STAGE_B 32768
__device__ __forceinline__ void gemm_mainloop(
    const __nv_bfloat16* const* srcs, uint32_t sbase, int tid,
    int wm, int wn, int lane, int K, float acc[4][8][4])
{
    const int nkc = K >> 5;
    const int lt  = lane >> 3;
    const int lr8 = lane & 7;

    #pragma unroll
    for (int st = 0; st < 2; st++) {
        const int kofs = st << 5;
        const uint32_t stb = sbase + st * STAGE_B;
        #pragma unroll
        for (int t = 0; t < 4; t++) {
            const char* s = (const char*)(srcs[t] + kofs);
            uint32_t db = stb + t * TILE8K;
            #pragma unroll
            for (int j = 0; j < 4; j++) {
                int idx = tid + j*128;
                int r = idx >> 2, c = idx & 3;
                cpa16(db + r*64 + ((c ^ ((r>>1)&3))<<4), s + (size_t)r*(K*2) + c*16);
            }
        }
        asm volatile("cp.async.commit_group;");
    }

    int buf = 0;
    for (int kc = 0; kc < nkc; kc++) {
        if (kc + 1 < nkc) asm volatile("cp.async.wait_group 1;");
        else              asm volatile("cp.async.wait_group 0;");
        __syncthreads();

        if (kc + 2 < nkc) {
            const int kofs = (kc + 2) << 5;
            int nb3 = buf + 2; if (nb3 >= 3) nb3 -= 3;
            const uint32_t stb = sbase + nb3 * STAGE_B;
            #pragma unroll
            for (int t = 0; t < 4; t++) {
                const char* s = (const char*)(srcs[t] + kofs);
                uint32_t db = stb + t * TILE8K;
                #pragma unroll
                for (int j = 0; j < 4; j++) {
                    int idx = tid + j*128;
                    int r = idx >> 2, c = idx & 3;
                    cpa16(db + r*64 + ((c ^ ((r>>1)&3))<<4), s + (size_t)r*(K*2) + c*16);
                }
            }
            asm volatile("cp.async.commit_group;");
        }

        const uint32_t abH = sbase + buf * STAGE_B;
        const uint32_t abL = abH + TILE8K;
        const uint32_t wbH = abH + 2 * TILE8K;
        const uint32_t wbL = abH + 3 * TILE8K;

        #pragma unroll
        for (int ka = 0; ka < 2; ka++) {
            uint32_t aH[4][4], aL[4][4], bH[8][2], bL[8][2];
            #pragma unroll
            for (int ma = 0; ma < 4; ma++) {
                int row = wm + ma*16 + ((lt & 1) << 3) + lr8;
                int ch  = (ka << 1) + (lt >> 1);
                uint32_t off = (uint32_t)(row*64 + ((ch ^ ((row>>1)&3)) << 4));
                ldsm4(aH[ma], abH + off);
                ldsm4(aL[ma], abL + off);
            }
            #pragma unroll
            for (int nb = 0; nb < 4; nb++) {
                int row = wn + nb*16 + ((lt >> 1) << 3) + lr8;
                int ch  = (ka << 1) + (lt & 1);
                uint32_t off = (uint32_t)(row*64 + ((ch ^ ((row>>1)&3)) << 4));
                uint32_t r[4];
                ldsm4(r, wbH + off);
                bH[2*nb][0]=r[0]; bH[2*nb][1]=r[1]; bH[2*nb+1][0]=r[2]; bH[2*nb+1][1]=r[3];
                ldsm4(r, wbL + off);
                bL[2*nb][0]=r[0]; bL[2*nb][1]=r[1]; bL[2*nb+1][0]=r[2]; bL[2*nb+1][1]=r[3];
            }
            #pragma unroll
            for (int ma = 0; ma < 4; ma++)
                #pragma unroll
                for (int na = 0; na < 8; na++)
                    mma_bf16(acc[ma][na], aH[ma], bH[na]);
            #pragma unroll
            for (int ma = 0; ma < 4; ma++)
                #pragma unroll
                for (int na = 0; na < 8; na++)
                    mma_bf16(acc[ma][na], aL[ma], bH[na]);
            #pragma unroll
            for (int ma = 0; ma < 4; ma++)
                #pragma unroll
                for (int na = 0; na < 8; na++)
                    mma_bf16(acc[ma][na], aH[ma], bL[na]);
        }
        buf++; if (buf >= 3) buf = 0;
    }
}

// ---------------------------------------------------------------------------
// Plain GEMM (out-projection): fp32 row-major C + bias.
// ---------------------------------------------------------------------------
__global__ __launch_bounds__(128) void gemm_tc(
    const __nv_bfloat16* __restrict__ Ah, const __nv_bfloat16* __restrict__ Al,
    const __nv_bfloat16* __restrict__ Wh, const __nv_bfloat16* __restrict__ Wl,
    const float* __restrict__ bias, float* __restrict__ C, int M, int N, int K)
{
    extern __shared__ __align__(1024) char sm[];
    const uint32_t sbase = smem_u32(sm);
    const int tid = threadIdx.x;
    const int wid = tid >> 5, lane = tid & 31;
    const int bm = blockIdx.y * 128, bn = blockIdx.x * 128;
    const int wm = (wid >> 1) * 64, wn = (wid & 1) * 64;

    const __nv_bfloat16* srcs[4] = {
        Ah + (size_t)bm * K, Al + (size_t)bm * K,
        Wh + (size_t)bn * K, Wl + (size_t)bn * K };

    float acc[4][8][4] = {};
    gemm_mainloop(srcs, sbase, tid, wm, wn, lane, K, acc);

    #pragma unroll
    for (int ma = 0; ma < 4; ma++) {
        int r = bm + wm + ma*16 + (lane >> 2);
        #pragma unroll
        for (int na = 0; na < 8; na++) {
            int col = bn + wn + na*8 + (lane & 3)*2;
            float2 b2 = *(const float2*)(bias + col);
            float2 v0 = { acc[ma][na][0] + b2.x, acc[ma][na][1] + b2.y };
            float2 v1 = { acc[ma][na][2] + b2.x, acc[ma][na][3] + b2.y };
            *(float2*)(C + (size_t)r * N + col)       = v0;
            *(float2*)(C + (size_t)(r + 8) * N + col) = v1;
        }
    }
}

// ---------------------------------------------------------------------------
// Fused QKV GEMM: blockIdx.z = 0(Q)/1(K)/2(V). Epilogue applies bias, then
// Q/K: RMSNorm(DK=64) + RoPE;  V: passthrough. Writes bf16 hi/lo head-major.
// ---------------------------------------------------------------------------
__global__ __launch_bounds__(128) void gemm_qkv(
    const __nv_bfloat16* __restrict__ Ah, const __nv_bfloat16* __restrict__ Al,
    const __nv_bfloat16* __restrict__ Wh, const __nv_bfloat16* __restrict__ Wl,
    size_t strideA, size_t strideW,
    const float* __restrict__ bq, const float* __restrict__ bk,
    const float* __restrict__ bv,
    const float* __restrict__ qn, const float* __restrict__ kn,
    const float* __restrict__ cs, const float* __restrict__ sn,
    __nv_bfloat16* __restrict__ Qh, __nv_bfloat16* __restrict__ Ql,
    __nv_bfloat16* __restrict__ Kh, __nv_bfloat16* __restrict__ Kl,
    __nv_bfloat16* __restrict__ Vh, __nv_bfloat16* __restrict__ Vl,
    int M, int N, int K)
{
    extern __shared__ __align__(1024) char sm[];
    const uint32_t sbase = smem_u32(sm);
    const int tid = threadIdx.x;
    const int wid = tid >> 5, lane = tid & 31;
    const int bm = blockIdx.y * 128, bn = blockIdx.x * 128;
    const int wm = (wid >> 1) * 64, wn = (wid & 1) * 64;
    const int z = blockIdx.z;
    const size_t zA = (size_t)z * strideA, zW = (size_t)z * strideW;

    const __nv_bfloat16* srcs[4] = {
        Ah + zA + (size_t)bm * K, Al + zA + (size_t)bm * K,
        Wh + zW + (size_t)bn * K, Wl + zW + (size_t)bn * K };

    float acc[4][8][4] = {};
    gemm_mainloop(srcs, sbase, tid, wm, wn, lane, K, acc);

    const float* bias = (z == 0) ? bq : (z == 1) ? bk : bv;
    __nv_bfloat16* OH = (z == 0) ? Qh : (z == 1) ? Kh : Vh;
    __nv_bfloat16* OL = (z == 0) ? Ql : (z == 1) ? Kl : Vl;

    const int lg = lane >> 2, tg = lane & 3;
    const int h = (bn + wn) >> 6;

    float2 bb[8];
    #pragma unroll
    for (int na = 0; na < 8; na++)
        bb[na] = *(const float2*)(bias + bn + wn + na*8 + tg*2);

    float wt[8][2];
    if (z < 2) {
        const float* w = (z == 0) ? qn : kn;
        #pragma unroll
        for (int na = 0; na < 8; na++) {
            float2 w2 = *(const float2*)(w + na*8 + tg*2);
            wt[na][0] = w2.x; wt[na][1] = w2.y;
        }
    }

    #pragma unroll
    for (int ma = 0; ma < 4; ma++) {
        #pragma unroll
        for (int half = 0; half < 2; half++) {
            int r = bm + wm + ma*16 + lg + half*8;
            int b = r >> 11, s = r & (Sq - 1);
            size_t ob = (((size_t)(b*16 + h))*Sq + s)*64;

            float v[8][2];
            float ss = 0.f;
            #pragma unroll
            for (int na = 0; na < 8; na++) {
                v[na][0] = acc[ma][na][2*half]   + bb[na].x;
                v[na][1] = acc[ma][na][2*half+1] + bb[na].y;
                ss += v[na][0]*v[na][0] + v[na][1]*v[na][1];
            }

            if (z == 2) {
                #pragma unroll
                for (int na = 0; na < 8; na++)
                    store_hilo(OH, OL, ob + na*8 + tg*2, v[na][0], v[na][1]);
            } else {
                ss += __shfl_xor_sync(0xffffffffu, ss, 1);
                ss += __shfl_xor_sync(0xffffffffu, ss, 2);
                float inv = rsqrtf(ss*(1.0f/64.0f) + 1e-6f);
                const float* crow = cs + (size_t)s*64;
                const float* srow = sn + (size_t)s*64;
                #pragma unroll
                for (int na = 0; na < 4; na++) {
                    int d = na*8 + tg*2;
                    float y0a = v[na][0]*inv*wt[na][0];
                    float y0b = v[na][1]*inv*wt[na][1];
                    float y1a = v[na+4][0]*inv*wt[na+4][0];
                    float y1b = v[na+4][1]*inv*wt[na+4][1];
                    float2 c0 = *(const float2*)(crow + d);
                    float2 s0 = *(const float2*)(srow + d);
                    float2 c1 = *(const float2*)(crow + d + 32);
                    float2 s1 = *(const float2*)(srow + d + 32);
                    float o0a = y0a*c0.x - y1a*s0.x;
                    float o0b = y0b*c0.y - y1b*s0.y;
                    float o1a = y1a*c1.x + y0a*s1.x;
                    float o1b = y1b*c1.y + y0b*s1.y;
                    store_hilo(OH, OL, ob + d,      o0a, o0b);
                    store_hilo(OH, OL, ob + d + 32, o1a, o1b);
                }
            }
        }
    }
}

// ---------------------------------------------------------------------------
// Flash attention, causal, split-KV x2 (blockIdx.z = KV half).
// Fixed-max softmax (post-RMSNorm bound: S in [-8,8]) makes partials
// combine by plain addition. Writes fp32 partial O + row sums l.
// ---------------------------------------------------------------------------
#define ATT_SMEM (32768 + 2*32768)
__global__ __launch_bounds__(256, 2) void flash_attn_tc(
    const __nv_bfloat16* __restrict__ Qh, const __nv_bfloat16* __restrict__ Ql,
    const __nv_bfloat16* __restrict__ Kh, const __nv_bfloat16* __restrict__ Kl,
    const __nv_bfloat16* __restrict__ Vh, const __nv_bfloat16* __restrict__ Vl,
    float* __restrict__ O0p, float* __restrict__ O1p,
    float* __restrict__ L0p, float* __restrict__ L1p)
{
    extern __shared__ __align__(1024) char sm[];
    const uint32_t sQ = smem_u32(sm);
    const uint32_t sStage = sQ + 32768;
    const int tid = threadIdx.x, wid = tid >> 5, lane = tid & 31;
    const int qb = gridDim.x - 1 - blockIdx.x;
    const int bh = blockIdx.y;
    const int sId = blockIdx.z;
    const int q0 = qb * 128;
    const size_t hb = (size_t)bh * Sq * DKq;

    float* Op = sId ? O1p : O0p;
    float* Lp = sId ? L1p : L0p;

    const char* gQh = (const char*)(Qh + hb + (size_t)q0*64);
    const char* gQl = (const char*)(Ql + hb + (size_t)q0*64);
    const char* gKh = (const char*)(Kh + hb);
    const char* gKl = (const char*)(Kl + hb);
    const char* gVh = (const char*)(Vh + hb);
    const char* gVl = (const char*)(Vl + hb);

    const int kb0 = sId * (qb + 1);
    const int kbN = kb0 + (qb + 1);

    #pragma unroll
    for (int j = 0; j < 4; j++) {
        int i = tid + j*256;
        int r = i >> 3, c = i & 7;
        uint32_t so = (uint32_t)(r*128 + ((c ^ (r&7)) << 4));
        cpa16(sQ + so,         gQh + r*128 + c*16);
        cpa16(sQ + 16384 + so, gQl + r*128 + c*16);
    }
    {
        const char* gs[4] = { gKh, gKl, gVh, gVl };
        #pragma unroll
        for (int t = 0; t < 4; t++)
            #pragma unroll
            for (int j = 0; j < 2; j++) {
                int i = tid + j*256;
                int r = i >> 3, c = i & 7;
                uint32_t so = (uint32_t)(r*128 + ((c ^ (r&7)) << 4));
                cpa16(sStage + t*8192 + so, gs[t] + (size_t)(kb0*64 + r)*128 + c*16);
            }
    }
    asm volatile("cp.async.commit_group;");

    float o[8][4] = {};
    float S[8][4];
    float l0 = 0.f, l1 = 0.f;
    uint32_t qfh[4][4];

    const int lg = lane >> 2;
    const int tg = lane & 3;
    const int lrow = (((lane >> 3) & 1) << 3) + (lane & 7);
    const int lsel = lane >> 4;

    const float c1 = 0.125f * 1.4426950408889634f;
    const float c2 = 8.0f  * 1.4426950408889634f;

    for (int kb = kb0; kb < kbN; kb++) {
        const int ib = kb - kb0;
        if (kb + 1 < kbN) {
            const uint32_t stb = sStage + ((ib+1) & 1) * 32768;
            const int kvr = (kb+1) * 64;
            const char* gs[4] = { gKh, gKl, gVh, gVl };
            #pragma unroll
            for (int t = 0; t < 4; t++)
                #pragma unroll
                for (int j = 0; j < 2; j++) {
                    int i = tid + j*256;
                    int r = i >> 3, c = i & 7;
                    uint32_t so = (uint32_t)(r*128 + ((c ^ (r&7)) << 4));
                    cpa16(stb + t*8192 + so, gs[t] + (size_t)(kvr + r)*128 + c*16);
                }
            asm volatile("cp.async.commit_group;");
            asm volatile("cp.async.wait_group 1;");
        } else {
            asm volatile("cp.async.wait_group 0;");
        }
        __syncthreads();

        if (ib == 0) {
            #pragma unroll
            for (int ka = 0; ka < 4; ka++) {
                int r = wid*16 + lrow;
                int c = 2*ka + lsel;
                ldsm4(qfh[ka], sQ + (uint32_t)(r*128 + ((c ^ (r&7)) << 4)));
            }
        }

        const bool active = (kb*64 <= q0 + wid*16 + 15);
        if (active) {
            const uint32_t bK = sStage + (ib & 1) * 32768;
            #pragma unroll
            for (int n = 0; n < 8; n++)
                #pragma unroll
                for (int x = 0; x < 4; x++) S[n][x] = 0.f;

            #pragma unroll
            for (int ka = 0; ka < 4; ka++) {
                uint32_t qlw[4];
                {
                    int r = wid*16 + lrow;
                    int c = 2*ka + lsel;
                    ldsm4(qlw, sQ + 16384 + (uint32_t)(r*128 + ((c ^ (r&7)) << 4)));
                }
                #pragma unroll
                for (int n16 = 0; n16 < 4; n16++) {
                    int r = n16*16 + lrow;
                    int c = 2*ka + lsel;
                    uint32_t off = (uint32_t)(r*128 + ((c ^ (r&7)) << 4));
                    uint32_t kh4[4], kl4[4];
                    ldsm4(kh4, bK + off);
                    ldsm4(kl4, bK + 8192 + off);
                    uint32_t bh0[2] = { kh4[0], kh4[2] }, bh1[2] = { kh4[1], kh4[3] };
                    uint32_t bl0[2] = { kl4[0], kl4[2] }, bl1[2] = { kl4[1], kl4[3] };
                    mma_bf16(S[2*n16],   qfh[ka], bh0);
                    mma_bf16(S[2*n16],   qlw,     bh0);
                    mma_bf16(S[2*n16],   qfh[ka], bl0);
                    mma_bf16(S[2*n16+1], qfh[ka], bh1);
                    mma_bf16(S[2*n16+1], qlw,     bh1);
                    mma_bf16(S[2*n16+1], qfh[ka], bl1);
                }
            }

            const int row0 = q0 + wid*16 + lg;
            const int row1 = row0 + 8;
            float sum0 = 0.f, sum1 = 0.f;
            if (kb >= 2*qb) {
                #pragma unroll
                for (int n = 0; n < 8; n++) {
                    int col0 = kb*64 + n*8 + tg*2;
                    float e0 = exp2f(fmaf(S[n][0], c1, -c2));
                    float e1 = exp2f(fmaf(S[n][1], c1, -c2));
                    float e2 = exp2f(fmaf(S[n][2], c1, -c2));
                    float e3 = exp2f(fmaf(S[n][3], c1, -c2));
                    if (col0     > row0) e0 = 0.f;
                    if (col0 + 1 > row0) e1 = 0.f;
                    if (col0     > row1) e2 = 0.f;
                    if (col0 + 1 > row1) e3 = 0.f;
                    S[n][0] = e0; S[n][1] = e1; S[n][2] = e2; S[n][3] = e3;
                    sum0 += e0 + e1;
                    sum1 += e2 + e3;
                }
            } else {
                #pragma unroll
                for (int n = 0; n < 8; n++) {
                    float e0 = exp2f(fmaf(S[n][0], c1, -c2));
                    float e1 = exp2f(fmaf(S[n][1], c1, -c2));
                    float e2 = exp2f(fmaf(S[n][2], c1, -c2));
                    float e3 = exp2f(fmaf(S[n][3], c1, -c2));
                    S[n][0] = e0; S[n][1] = e1; S[n][2] = e2; S[n][3] = e3;
                    sum0 += e0 + e1;
                    sum1 += e2 + e3;
                }
            }
            sum0 += __shfl_xor_sync(0xffffffffu, sum0, 1);
            sum0 += __shfl_xor_sync(0xffffffffu, sum0, 2);
            sum1 += __shfl_xor_sync(0xffffffffu, sum1, 1);
            sum1 += __shfl_xor_sync(0xffffffffu, sum1, 2);
            l0 += sum0;
            l1 += sum1;

            const uint32_t bV = bK + 16384;
            #pragma unroll
            for (int ka = 0; ka < 4; ka++) {
                uint32_t ah[4], al[4];
                #pragma unroll
                for (int half = 0; half < 2; half++) {
                    const float* s4 = S[2*ka + half];
                    __nv_bfloat16 hA = __float2bfloat16(s4[0]);
                    __nv_bfloat16 hB = __float2bfloat16(s4[1]);
                    __nv_bfloat16 hC = __float2bfloat16(s4[2]);
                    __nv_bfloat16 hD = __float2bfloat16(s4[3]);
                    ah[2*half+0] = pack_bf2(__bfloat162float(hA), __bfloat162float(hB));
                    ah[2*half+1] = pack_bf2(__bfloat162float(hC), __bfloat162float(hD));
                    al[2*half+0] = pack_bf2(s4[0]-__bfloat162float(hA), s4[1]-__bfloat162float(hB));
                    al[2*half+1] = pack_bf2(s4[2]-__bfloat162float(hC), s4[3]-__bfloat162float(hD));
                }
                #pragma unroll
                for (int ndp = 0; ndp < 4; ndp++) {
                    int r = ka*16 + lrow;
                    int c = 2*ndp + lsel;
                    uint32_t off = (uint32_t)(r*128 + ((c ^ (r&7)) << 4));
                    uint32_t vh4[4], vl4[4];
                    ldsm4t(vh4, bV + off);
                    ldsm4t(vl4, bV + 8192 + off);
                    uint32_t bh0[2] = { vh4[0], vh4[1] }, bh1[2] = { vh4[2], vh4[3] };
                    uint32_t bl0[2] = { vl4[0], vl4[1] }, bl1[2] = { vl4[2], vl4[3] };
                    mma_bf16(o[2*ndp],   ah, bh0);
                    mma_bf16(o[2*ndp],   al, bh0);
                    mma_bf16(o[2*ndp],   ah, bl0);
                    mma_bf16(o[2*ndp+1], ah, bh1);
                    mma_bf16(o[2*ndp+1], al, bh1);
                    mma_bf16(o[2*ndp+1], ah, bl1);
                }
            }
        }
        __syncthreads();
    }

    // epilogue: fp32 partial O ([bs][h*64+d]) + l partials ([bh][s])
    const int b = bh >> 4, h = bh & 15;
    const int r0g = b*Sq + q0 + wid*16 + lg;
    size_t base0 = (size_t)r0g * Dq + h*64 + tg*2;
    size_t base1 = base0 + (size_t)8 * Dq;
    #pragma unroll
    for (int n = 0; n < 8; n++) {
        *(float2*)(Op + base0 + n*8) = make_float2(o[n][0], o[n][1]);
        *(float2*)(Op + base1 + n*8) = make_float2(o[n][2], o[n][3]);
    }
    if (tg == 0) {
        size_t li = (size_t)bh * Sq + q0 + wid*16 + lg;
        Lp[li]     = l0;
        Lp[li + 8] = l1;
    }
}

// ---------------------------------------------------------------------------
// Combine split-KV partials: O = (A+B)/(lA+lB), write bf16 hi/lo [bs][h*64+d]
// ---------------------------------------------------------------------------
__global__ __launch_bounds__(256) void combine_kv(
    const float* __restrict__ A, const float* __restrict__ B,
    const float* __restrict__ LA, const float* __restrict__ LB,
    __nv_bfloat16* __restrict__ OH, __nv_bfloat16* __restrict__ OL)
{
    int i = blockIdx.x * blockDim.x + threadIdx.x;   // float4 index
    int bs = i >> 8, c4 = i & 255;
    int h = c4 >> 4;
    int b = bs >> 11, s = bs & (Sq - 1);
    size_t li = ((size_t)(b*16 + h)) * Sq + s;
    float inv = 1.0f / (LA[li] + LB[li]);
    float4 a = ((const float4*)A)[i];
    float4 c = ((const float4*)B)[i];
    float x0 = (a.x + c.x) * inv, x1 = (a.y + c.y) * inv;
    float x2 = (a.z + c.z) * inv, x3 = (a.w + c.w) * inv;
    size_t o = (size_t)i * 4;
    store_hilo(OH, OL, o,     x0, x1);
    store_hilo(OH, OL, o + 2, x2, x3);
}

// ---------------------------------------------------------------------------
extern "C" void kernel_launch(void* const* d_in, const int* in_sizes, int n_in,
                              void* d_out, int out_size)
{
    (void)in_sizes; (void)n_in; (void)out_size;
    const float* q  = (const float*)d_in[0];
    const float* k  = (const float*)d_in[1];
    const float* v  = (const float*)d_in[2];
    const float* cs = (const float*)d_in[4];
    const float* sn = (const float*)d_in[5];
    const float* wq = (const float*)d_in[6];
    const float* bq = (const float*)d_in[7];
    const float* wk = (const float*)d_in[8];
    const float* bk = (const float*)d_in[9];
    const float* wv = (const float*)d_in[10];
    const float* bv = (const float*)d_in[11];
    const float* wo = (const float*)d_in[12];
    const float* bo = (const float*)d_in[13];
    const float* qn = (const float*)d_in[14];
    const float* kn = (const float*)d_in[15];
    float* out = (float*)d_out;

    __nv_bfloat16 *aH, *aL, *wH, *wL, *qh, *ql, *kh, *kl, *vh, *vl;
    float *pO0, *pO1, *pL0, *pL1;
    cudaGetSymbolAddress((void**)&aH, g_actH);
    cudaGetSymbolAddress((void**)&aL, g_actL);
    cudaGetSymbolAddress((void**)&wH, g_wH);
    cudaGetSymbolAddress((void**)&wL, g_wL);
    cudaGetSymbolAddress((void**)&qh, g_Qh);
    cudaGetSymbolAddress((void**)&ql, g_Ql);
    cudaGetSymbolAddress((void**)&kh, g_Kh);
    cudaGetSymbolAddress((void**)&kl, g_Kl);
    cudaGetSymbolAddress((void**)&vh, g_Vh);
    cudaGetSymbolAddress((void**)&vl, g_Vl);
    cudaGetSymbolAddress((void**)&pO0, g_O0);
    cudaGetSymbolAddress((void**)&pO1, g_O1);
    cudaGetSymbolAddress((void**)&pL0, g_L0);
    cudaGetSymbolAddress((void**)&pL1, g_L1);

    const size_t actN = (size_t)Mq*Dq, wN = (size_t)Dq*Dq;
    const int actN4 = (int)(actN/4), wN4 = (int)(wN/4);
    const int gsm = 3 * STAGE_B;   // 98304
    cudaFuncSetAttribute(gemm_tc,  cudaFuncAttributeMaxDynamicSharedMemorySize, gsm);
    cudaFuncSetAttribute(gemm_qkv, cudaFuncAttributeMaxDynamicSharedMemorySize, gsm);
    cudaFuncSetAttribute(flash_attn_tc, cudaFuncAttributeMaxDynamicSharedMemorySize, ATT_SMEM);

    split_multi<<<dim3(actN4/256, 3), 256>>>(q, k, v, v, aH, aL, actN4);
    split_multi<<<dim3(wN4/256, 4), 256>>>(wq, wk, wv, wo, wH, wL, wN4);

    gemm_qkv<<<dim3(Dq/128, Mq/128, 3), 128, gsm>>>(
        aH, aL, wH, wL, actN, wN, bq, bk, bv, qn, kn, cs, sn,
        qh, ql, kh, kl, vh, vl, Mq, Dq, Dq);

    // split-KV attention: z = KV half; partials combined below
    flash_attn_tc<<<dim3(Sq/128, Bq*Hq, 2), 256, ATT_SMEM>>>(
        qh, ql, kh, kl, vh, vl, pO0, pO1, pL0, pL1);
    combine_kv<<<Mq*Dq/4/256, 256>>>(pO0, pO1, pL0, pL1, aH, aL);

    gemm_tc<<<dim3(Dq/128, Mq/128), 128, gsm>>>(aH, aL, wH + 3*wN, wL + 3*wN, bo, out, Mq, Dq, Dq);
}

// round 15
// speedup vs baseline: 1.3697x; 1.2732x over previous
#include <cuda_runtime.h>
#include <cuda_fp16.h>
#include <math.h>
#include <stdint.h>

#define Bq  2
#define Sq  2048
#define Dq  1024
#define Hq  16
#define DKq 64
#define Mq  (Bq*Sq)   // 4096

// activation hi/lo: 3 slots (q,k,v inputs); slot 0 reused after attention
__device__ __half g_actH[(size_t)3*Mq*Dq];
__device__ __half g_actL[(size_t)3*Mq*Dq];
// weight fp16 (hi only): 4 slots (wq,wk,wv,wo)
__device__ __half g_wH[(size_t)4*Dq*Dq];
// head-major [b*16+h][s][64] fp16 attention operands
__device__ __half g_Qh[(size_t)Mq*Dq];
__device__ __half g_Ql[(size_t)Mq*Dq];
__device__ __half g_Kh[(size_t)Mq*Dq];
__device__ __half g_Vh[(size_t)Mq*Dq];
// split-KV partial O (fp32) and row sums l
__device__ float g_O0[(size_t)Mq*Dq];
__device__ float g_O1[(size_t)Mq*Dq];
__device__ float g_L0[(size_t)Bq*Hq*Sq];
__device__ float g_L1[(size_t)Bq*Hq*Sq];

// ---------------------------------------------------------------------------
// helpers
// ---------------------------------------------------------------------------
__device__ __forceinline__ uint32_t smem_u32(const void* p) {
    uint32_t a;
    asm("{ .reg .u64 t; cvta.to.shared.u64 t, %1; cvt.u32.u64 %0, t; }" : "=r"(a) : "l"(p));
    return a;
}
__device__ __forceinline__ void cpa16(uint32_t saddr, const void* g) {
    asm volatile("cp.async.ca.shared.global [%0], [%1], 16;" :: "r"(saddr), "l"(g));
}
__device__ __forceinline__ void ldsm4(uint32_t* r, uint32_t addr) {
    asm volatile("ldmatrix.sync.aligned.m8n8.x4.shared.b16 {%0,%1,%2,%3}, [%4];"
        : "=r"(r[0]), "=r"(r[1]), "=r"(r[2]), "=r"(r[3]) : "r"(addr));
}
__device__ __forceinline__ void ldsm4t(uint32_t* r, uint32_t addr) {
    asm volatile("ldmatrix.sync.aligned.m8n8.x4.trans.shared.b16 {%0,%1,%2,%3}, [%4];"
        : "=r"(r[0]), "=r"(r[1]), "=r"(r[2]), "=r"(r[3]) : "r"(addr));
}
__device__ __forceinline__ void mma_f16(float* c, const uint32_t* a, const uint32_t* b) {
    asm volatile("mma.sync.aligned.m16n8k16.row.col.f32.f16.f16.f32 "
        "{%0,%1,%2,%3}, {%4,%5,%6,%7}, {%8,%9}, {%0,%1,%2,%3};"
        : "+f"(c[0]), "+f"(c[1]), "+f"(c[2]), "+f"(c[3])
        : "r"(a[0]), "r"(a[1]), "r"(a[2]), "r"(a[3]), "r"(b[0]), "r"(b[1]));
}
__device__ __forceinline__ uint32_t pack_h2(float lo, float hi) {
    half2 t = __floats2half2_rn(lo, hi);
    return *(uint32_t*)&t;
}
__device__ __forceinline__ void store_hilo(__half* H, __half* L,
                                           size_t o, float x, float y) {
    __half hx = __float2half_rn(x);
    __half hy = __float2half_rn(y);
    *(half2*)(H + o) = __halves2half2(hx, hy);
    *(half2*)(L + o) = __halves2half2(
        __float2half_rn(x - __half2float(hx)),
        __float2half_rn(y - __half2float(hy)));
}

// ---------------------------------------------------------------------------
// fp32 -> fp16 hi/lo split (activations); grid.y selects tensor (3 slots).
// ---------------------------------------------------------------------------
__global__ __launch_bounds__(256) void split_act(
    const float* __restrict__ x0, const float* __restrict__ x1,
    const float* __restrict__ x2,
    __half* __restrict__ h, __half* __restrict__ l, int n4)
{
    const float* srcs[3] = { x0, x1, x2 };
    const float* x = srcs[blockIdx.y];
    size_t slot = (size_t)blockIdx.y * 2u * (size_t)n4;   // half2 units
    int i = blockIdx.x * blockDim.x + threadIdx.x;
    if (i >= n4) return;
    float4 v = ((const float4*)x)[i];
    __half h0 = __float2half_rn(v.x), h1 = __float2half_rn(v.y);
    __half h2 = __float2half_rn(v.z), h3 = __float2half_rn(v.w);
    ((half2*)h)[slot + 2*i]   = __halves2half2(h0, h1);
    ((half2*)h)[slot + 2*i+1] = __halves2half2(h2, h3);
    ((half2*)l)[slot + 2*i]   = __halves2half2(
        __float2half_rn(v.x - __half2float(h0)),
        __float2half_rn(v.y - __half2float(h1)));
    ((half2*)l)[slot + 2*i+1] = __halves2half2(
        __float2half_rn(v.z - __half2float(h2)),
        __float2half_rn(v.w - __half2float(h3)));
}

// fp32 -> fp16 plain convert (weights); grid.y selects one of 4 slots.
__global__ __launch_bounds__(256) void conv_w(
    const float* __restrict__ x0, const float* __restrict__ x1,
    const float* __restrict__ x2, const float* __restrict__ x3,
    __half* __restrict__ h, int n4)
{
    const float* srcs[4] = { x0, x1, x2, x3 };
    const float* x = srcs[blockIdx.y];
    size_t slot = (size_t)blockIdx.y * 2u * (size_t)n4;
    int i = blockIdx.x * blockDim.x + threadIdx.x;
    if (i >= n4) return;
    float4 v = ((const float4*)x)[i];
    ((half2*)h)[slot + 2*i]   = __floats2half2_rn(v.x, v.y);
    ((half2*)h)[slot + 2*i+1] = __floats2half2_rn(v.z, v.w);
}

// ---------------------------------------------------------------------------
// GEMM mainloop (fp16 2-term: acc += Ah*Wh + Al*Wh). 128x128 CTA tile,
// 4 warps (64x64), K-chunk 32, 3-stage cp.async pipeline.
// smem per stage (24KB): Ah | Al | Wh, each 128 rows x 64B.
// ---------------------------------------------------------------------------
#define TILE8K 8192
#define STAGE_B 24576
__device__ __forceinline__ void gemm_mainloop(
    const __half* const* srcs, uint32_t sbase, int tid,
    int wm, int wn, int lane, int K, float acc[4][8][4])
{
    const int nkc = K >> 5;
    const int lt  = lane >> 3;
    const int lr8 = lane & 7;

    #pragma unroll
    for (int st = 0; st < 2; st++) {
        const int kofs = st << 5;
        const uint32_t stb = sbase + st * STAGE_B;
        #pragma unroll
        for (int t = 0; t < 3; t++) {
            const char* s = (const char*)(srcs[t] + kofs);
            uint32_t db = stb + t * TILE8K;
            #pragma unroll
            for (int j = 0; j < 4; j++) {
                int idx = tid + j*128;
                int r = idx >> 2, c = idx & 3;
                cpa16(db + r*64 + ((c ^ ((r>>1)&3))<<4), s + (size_t)r*(K*2) + c*16);
            }
        }
        asm volatile("cp.async.commit_group;");
    }

    int buf = 0;
    for (int kc = 0; kc < nkc; kc++) {
        if (kc + 1 < nkc) asm volatile("cp.async.wait_group 1;");
        else              asm volatile("cp.async.wait_group 0;");
        __syncthreads();

        if (kc + 2 < nkc) {
            const int kofs = (kc + 2) << 5;
            int nb3 = buf + 2; if (nb3 >= 3) nb3 -= 3;
            const uint32_t stb = sbase + nb3 * STAGE_B;
            #pragma unroll
            for (int t = 0; t < 3; t++) {
                const char* s = (const char*)(srcs[t] + kofs);
                uint32_t db = stb + t * TILE8K;
                #pragma unroll
                for (int j = 0; j < 4; j++) {
                    int idx = tid + j*128;
                    int r = idx >> 2, c = idx & 3;
                    cpa16(db + r*64 + ((c ^ ((r>>1)&3))<<4), s + (size_t)r*(K*2) + c*16);
                }
            }
            asm volatile("cp.async.commit_group;");
        }

        const uint32_t abH = sbase + buf * STAGE_B;
        const uint32_t abL = abH + TILE8K;
        const uint32_t wbH = abH + 2 * TILE8K;

        #pragma unroll
        for (int ka = 0; ka < 2; ka++) {
            uint32_t aH[4][4], aL[4][4], bH[8][2];
            #pragma unroll
            for (int ma = 0; ma < 4; ma++) {
                int row = wm + ma*16 + ((lt & 1) << 3) + lr8;
                int ch  = (ka << 1) + (lt >> 1);
                uint32_t off = (uint32_t)(row*64 + ((ch ^ ((row>>1)&3)) << 4));
                ldsm4(aH[ma], abH + off);
                ldsm4(aL[ma], abL + off);
            }
            #pragma unroll
            for (int nb = 0; nb < 4; nb++) {
                int row = wn + nb*16 + ((lt >> 1) << 3) + lr8;
                int ch  = (ka << 1) + (lt & 1);
                uint32_t off = (uint32_t)(row*64 + ((ch ^ ((row>>1)&3)) << 4));
                uint32_t r[4];
                ldsm4(r, wbH + off);
                bH[2*nb][0]=r[0]; bH[2*nb][1]=r[1]; bH[2*nb+1][0]=r[2]; bH[2*nb+1][1]=r[3];
            }
            #pragma unroll
            for (int ma = 0; ma < 4; ma++)
                #pragma unroll
                for (int na = 0; na < 8; na++)
                    mma_f16(acc[ma][na], aH[ma], bH[na]);
            #pragma unroll
            for (int ma = 0; ma < 4; ma++)
                #pragma unroll
                for (int na = 0; na < 8; na++)
                    mma_f16(acc[ma][na], aL[ma], bH[na]);
        }
        buf++; if (buf >= 3) buf = 0;
    }
}

// ---------------------------------------------------------------------------
// Plain GEMM (out-projection): fp32 row-major C + bias.
// ---------------------------------------------------------------------------
__global__ __launch_bounds__(128) void gemm_tc(
    const __half* __restrict__ Ah, const __half* __restrict__ Al,
    const __half* __restrict__ Wh,
    const float* __restrict__ bias, float* __restrict__ C, int M, int N, int K)
{
    extern __shared__ __align__(1024) char sm[];
    const uint32_t sbase = smem_u32(sm);
    const int tid = threadIdx.x;
    const int wid = tid >> 5, lane = tid & 31;
    const int bm = blockIdx.y * 128, bn = blockIdx.x * 128;
    const int wm = (wid >> 1) * 64, wn = (wid & 1) * 64;

    const __half* srcs[3] = {
        Ah + (size_t)bm * K, Al + (size_t)bm * K, Wh + (size_t)bn * K };

    float acc[4][8][4] = {};
    gemm_mainloop(srcs, sbase, tid, wm, wn, lane, K, acc);

    #pragma unroll
    for (int ma = 0; ma < 4; ma++) {
        int r = bm + wm + ma*16 + (lane >> 2);
        #pragma unroll
        for (int na = 0; na < 8; na++) {
            int col = bn + wn + na*8 + (lane & 3)*2;
            float2 b2 = *(const float2*)(bias + col);
            float2 v0 = { acc[ma][na][0] + b2.x, acc[ma][na][1] + b2.y };
            float2 v1 = { acc[ma][na][2] + b2.x, acc[ma][na][3] + b2.y };
            *(float2*)(C + (size_t)r * N + col)       = v0;
            *(float2*)(C + (size_t)(r + 8) * N + col) = v1;
        }
    }
}

// ---------------------------------------------------------------------------
// Fused QKV GEMM: blockIdx.z = 0(Q)/1(K)/2(V). Epilogue: bias, then
// Q: norm+rope -> Qh/Ql;  K: norm+rope -> Kh only;  V: passthrough -> Vh.
// ---------------------------------------------------------------------------
__global__ __launch_bounds__(128) void gemm_qkv(
    const __half* __restrict__ Ah, const __half* __restrict__ Al,
    const __half* __restrict__ Wh, size_t strideA, size_t strideW,
    const float* __restrict__ bq, const float* __restrict__ bk,
    const float* __restrict__ bv,
    const float* __restrict__ qn, const float* __restrict__ kn,
    const float* __restrict__ cs, const float* __restrict__ sn,
    __half* __restrict__ Qh, __half* __restrict__ Ql,
    __half* __restrict__ Kh, __half* __restrict__ Vh,
    int M, int N, int K)
{
    extern __shared__ __align__(1024) char sm[];
    const uint32_t sbase = smem_u32(sm);
    const int tid = threadIdx.x;
    const int wid = tid >> 5, lane = tid & 31;
    const int bm = blockIdx.y * 128, bn = blockIdx.x * 128;
    const int wm = (wid >> 1) * 64, wn = (wid & 1) * 64;
    const int z = blockIdx.z;
    const size_t zA = (size_t)z * strideA, zW = (size_t)z * strideW;

    const __half* srcs[3] = {
        Ah + zA + (size_t)bm * K, Al + zA + (size_t)bm * K,
        Wh + zW + (size_t)bn * K };

    float acc[4][8][4] = {};
    gemm_mainloop(srcs, sbase, tid, wm, wn, lane, K, acc);

    const float* bias = (z == 0) ? bq : (z == 1) ? bk : bv;

    const int lg = lane >> 2, tg = lane & 3;
    const int h = (bn + wn) >> 6;

    float2 bb[8];
    #pragma unroll
    for (int na = 0; na < 8; na++)
        bb[na] = *(const float2*)(bias + bn + wn + na*8 + tg*2);

    float wt[8][2];
    if (z < 2) {
        const float* w = (z == 0) ? qn : kn;
        #pragma unroll
        for (int na = 0; na < 8; na++) {
            float2 w2 = *(const float2*)(w + na*8 + tg*2);
            wt[na][0] = w2.x; wt[na][1] = w2.y;
        }
    }

    #pragma unroll
    for (int ma = 0; ma < 4; ma++) {
        #pragma unroll
        for (int half_ = 0; half_ < 2; half_++) {
            int r = bm + wm + ma*16 + lg + half_*8;
            int b = r >> 11, s = r & (Sq - 1);
            size_t ob = (((size_t)(b*16 + h))*Sq + s)*64;

            float v[8][2];
            float ss = 0.f;
            #pragma unroll
            for (int na = 0; na < 8; na++) {
                v[na][0] = acc[ma][na][2*half_]   + bb[na].x;
                v[na][1] = acc[ma][na][2*half_+1] + bb[na].y;
                ss += v[na][0]*v[na][0] + v[na][1]*v[na][1];
            }

            if (z == 2) {
                #pragma unroll
                for (int na = 0; na < 8; na++)
                    *(half2*)(Vh + ob + na*8 + tg*2) =
                        __floats2half2_rn(v[na][0], v[na][1]);
            } else {
                ss += __shfl_xor_sync(0xffffffffu, ss, 1);
                ss += __shfl_xor_sync(0xffffffffu, ss, 2);
                float inv = rsqrtf(ss*(1.0f/64.0f) + 1e-6f);
                const float* crow = cs + (size_t)s*64;
                const float* srow = sn + (size_t)s*64;
                #pragma unroll
                for (int na = 0; na < 4; na++) {
                    int d = na*8 + tg*2;
                    float y0a = v[na][0]*inv*wt[na][0];
                    float y0b = v[na][1]*inv*wt[na][1];
                    float y1a = v[na+4][0]*inv*wt[na+4][0];
                    float y1b = v[na+4][1]*inv*wt[na+4][1];
                    float2 c0 = *(const float2*)(crow + d);
                    float2 s0 = *(const float2*)(srow + d);
                    float2 c1 = *(const float2*)(crow + d + 32);
                    float2 s1 = *(const float2*)(srow + d + 32);
                    float o0a = y0a*c0.x - y1a*s0.x;
                    float o0b = y0b*c0.y - y1b*s0.y;
                    float o1a = y1a*c1.x + y0a*s1.x;
                    float o1b = y1b*c1.y + y0b*s1.y;
                    if (z == 0) {
                        store_hilo(Qh, Ql, ob + d,      o0a, o0b);
                        store_hilo(Qh, Ql, ob + d + 32, o1a, o1b);
                    } else {
                        *(half2*)(Kh + ob + d)      = __floats2half2_rn(o0a, o0b);
                        *(half2*)(Kh + ob + d + 32) = __floats2half2_rn(o1a, o1b);
                    }
                }
            }
        }
    }
}

// ---------------------------------------------------------------------------
// Flash attention, causal, split-KV x2. fp16: Q hi/lo, K hi, P hi/lo, V hi.
// Fixed-max softmax (S in [-8,8]); partials combine by addition.
// smem: Qh|Ql 32KB + 2 stages x (Kh|Vh) 16KB = 64KB.
// ---------------------------------------------------------------------------
#define ATT_SMEM 65536
__global__ __launch_bounds__(256, 2) void flash_attn_tc(
    const __half* __restrict__ Qh, const __half* __restrict__ Ql,
    const __half* __restrict__ Kh, const __half* __restrict__ Vh,
    float* __restrict__ O0p, float* __restrict__ O1p,
    float* __restrict__ L0p, float* __restrict__ L1p)
{
    extern __shared__ __align__(1024) char sm[];
    const uint32_t sQ = smem_u32(sm);
    const uint32_t sStage = sQ + 32768;
    const int tid = threadIdx.x, wid = tid >> 5, lane = tid & 31;
    const int qb = gridDim.x - 1 - blockIdx.x;
    const int bh = blockIdx.y;
    const int sId = blockIdx.z;
    const int q0 = qb * 128;
    const size_t hb = (size_t)bh * Sq * DKq;

    float* Op = sId ? O1p : O0p;
    float* Lp = sId ? L1p : L0p;

    const char* gQh = (const char*)(Qh + hb + (size_t)q0*64);
    const char* gQl = (const char*)(Ql + hb + (size_t)q0*64);
    const char* gKh = (const char*)(Kh + hb);
    const char* gVh = (const char*)(Vh + hb);

    const int kb0 = sId * (qb + 1);
    const int kbN = kb0 + (qb + 1);

    #pragma unroll
    for (int j = 0; j < 4; j++) {
        int i = tid + j*256;
        int r = i >> 3, c = i & 7;
        uint32_t so = (uint32_t)(r*128 + ((c ^ (r&7)) << 4));
        cpa16(sQ + so,         gQh + r*128 + c*16);
        cpa16(sQ + 16384 + so, gQl + r*128 + c*16);
    }
    {
        const char* gs[2] = { gKh, gVh };
        #pragma unroll
        for (int t = 0; t < 2; t++)
            #pragma unroll
            for (int j = 0; j < 2; j++) {
                int i = tid + j*256;
                int r = i >> 3, c = i & 7;
                uint32_t so = (uint32_t)(r*128 + ((c ^ (r&7)) << 4));
                cpa16(sStage + t*8192 + so, gs[t] + (size_t)(kb0*64 + r)*128 + c*16);
            }
    }
    asm volatile("cp.async.commit_group;");

    float o[8][4] = {};
    float S[8][4];
    float l0 = 0.f, l1 = 0.f;
    uint32_t qfh[4][4];

    const int lg = lane >> 2;
    const int tg = lane & 3;
    const int lrow = (((lane >> 3) & 1) << 3) + (lane & 7);
    const int lsel = lane >> 4;

    const float c1 = 0.125f * 1.4426950408889634f;
    const float c2 = 8.0f  * 1.4426950408889634f;

    for (int kb = kb0; kb < kbN; kb++) {
        const int ib = kb - kb0;
        if (kb + 1 < kbN) {
            const uint32_t stb = sStage + ((ib+1) & 1) * 16384;
            const int kvr = (kb+1) * 64;
            const char* gs[2] = { gKh, gVh };
            #pragma unroll
            for (int t = 0; t < 2; t++)
                #pragma unroll
                for (int j = 0; j < 2; j++) {
                    int i = tid + j*256;
                    int r = i >> 3, c = i & 7;
                    uint32_t so = (uint32_t)(r*128 + ((c ^ (r&7)) << 4));
                    cpa16(stb + t*8192 + so, gs[t] + (size_t)(kvr + r)*128 + c*16);
                }
            asm volatile("cp.async.commit_group;");
            asm volatile("cp.async.wait_group 1;");
        } else {
            asm volatile("cp.async.wait_group 0;");
        }
        __syncthreads();

        if (ib == 0) {
            #pragma unroll
            for (int ka = 0; ka < 4; ka++) {
                int r = wid*16 + lrow;
                int c = 2*ka + lsel;
                ldsm4(qfh[ka], sQ + (uint32_t)(r*128 + ((c ^ (r&7)) << 4)));
            }
        }

        const bool active = (kb*64 <= q0 + wid*16 + 15);
        if (active) {
            const uint32_t bK = sStage + (ib & 1) * 16384;
            #pragma unroll
            for (int n = 0; n < 8; n++)
                #pragma unroll
                for (int x = 0; x < 4; x++) S[n][x] = 0.f;

            #pragma unroll
            for (int ka = 0; ka < 4; ka++) {
                uint32_t qlw[4];
                {
                    int r = wid*16 + lrow;
                    int c = 2*ka + lsel;
                    ldsm4(qlw, sQ + 16384 + (uint32_t)(r*128 + ((c ^ (r&7)) << 4)));
                }
                #pragma unroll
                for (int n16 = 0; n16 < 4; n16++) {
                    int r = n16*16 + lrow;
                    int c = 2*ka + lsel;
                    uint32_t off = (uint32_t)(r*128 + ((c ^ (r&7)) << 4));
                    uint32_t kh4[4];
                    ldsm4(kh4, bK + off);
                    uint32_t bh0[2] = { kh4[0], kh4[2] }, bh1[2] = { kh4[1], kh4[3] };
                    mma_f16(S[2*n16],   qfh[ka], bh0);
                    mma_f16(S[2*n16],   qlw,     bh0);
                    mma_f16(S[2*n16+1], qfh[ka], bh1);
                    mma_f16(S[2*n16+1], qlw,     bh1);
                }
            }

            const int row0 = q0 + wid*16 + lg;
            const int row1 = row0 + 8;
            float sum0 = 0.f, sum1 = 0.f;
            if (kb >= 2*qb) {
                #pragma unroll
                for (int n = 0; n < 8; n++) {
                    int col0 = kb*64 + n*8 + tg*2;
                    float e0 = exp2f(fmaf(S[n][0], c1, -c2));
                    float e1 = exp2f(fmaf(S[n][1], c1, -c2));
                    float e2 = exp2f(fmaf(S[n][2], c1, -c2));
                    float e3 = exp2f(fmaf(S[n][3], c1, -c2));
                    if (col0     > row0) e0 = 0.f;
                    if (col0 + 1 > row0) e1 = 0.f;
                    if (col0     > row1) e2 = 0.f;
                    if (col0 + 1 > row1) e3 = 0.f;
                    S[n][0] = e0; S[n][1] = e1; S[n][2] = e2; S[n][3] = e3;
                    sum0 += e0 + e1;
                    sum1 += e2 + e3;
                }
            } else {
                #pragma unroll
                for (int n = 0; n < 8; n++) {
                    float e0 = exp2f(fmaf(S[n][0], c1, -c2));
                    float e1 = exp2f(fmaf(S[n][1], c1, -c2));
                    float e2 = exp2f(fmaf(S[n][2], c1, -c2));
                    float e3 = exp2f(fmaf(S[n][3], c1, -c2));
                    S[n][0] = e0; S[n][1] = e1; S[n][2] = e2; S[n][3] = e3;
                    sum0 += e0 + e1;
                    sum1 += e2 + e3;
                }
            }
            sum0 += __shfl_xor_sync(0xffffffffu, sum0, 1);
            sum0 += __shfl_xor_sync(0xffffffffu, sum0, 2);
            sum1 += __shfl_xor_sync(0xffffffffu, sum1, 1);
            sum1 += __shfl_xor_sync(0xffffffffu, sum1, 2);
            l0 += sum0;
            l1 += sum1;

            const uint32_t bV = bK + 8192;
            #pragma unroll
            for (int ka = 0; ka < 4; ka++) {
                uint32_t ah[4], al[4];
                #pragma unroll
                for (int half_ = 0; half_ < 2; half_++) {
                    const float* s4 = S[2*ka + half_];
                    __half hA = __float2half_rn(s4[0]);
                    __half hB = __float2half_rn(s4[1]);
                    __half hC = __float2half_rn(s4[2]);
                    __half hD = __float2half_rn(s4[3]);
                    ah[2*half_+0] = pack_h2(__half2float(hA), __half2float(hB));
                    ah[2*half_+1] = pack_h2(__half2float(hC), __half2float(hD));
                    al[2*half_+0] = pack_h2(s4[0]-__half2float(hA), s4[1]-__half2float(hB));
                    al[2*half_+1] = pack_h2(s4[2]-__half2float(hC), s4[3]-__half2float(hD));
                }
                #pragma unroll
                for (int ndp = 0; ndp < 4; ndp++) {
                    int r = ka*16 + lrow;
                    int c = 2*ndp + lsel;
                    uint32_t off = (uint32_t)(r*128 + ((c ^ (r&7)) << 4));
                    uint32_t vh4[4];
                    ldsm4t(vh4, bV + off);
                    uint32_t bh0[2] = { vh4[0], vh4[1] }, bh1[2] = { vh4[2], vh4[3] };
                    mma_f16(o[2*ndp],   ah, bh0);
                    mma_f16(o[2*ndp],   al, bh0);
                    mma_f16(o[2*ndp+1], ah, bh1);
                    mma_f16(o[2*ndp+1], al, bh1);
                }
            }
        }
        __syncthreads();
    }

    const int b = bh >> 4, h = bh & 15;
    const int r0g = b*Sq + q0 + wid*16 + lg;
    size_t base0 = (size_t)r0g * Dq + h*64 + tg*2;
    size_t base1 = base0 + (size_t)8 * Dq;
    #pragma unroll
    for (int n = 0; n < 8; n++) {
        *(float2*)(Op + base0 + n*8) = make_float2(o[n][0], o[n][1]);
        *(float2*)(Op + base1 + n*8) = make_float2(o[n][2], o[n][3]);
    }
    if (tg == 0) {
        size_t li = (size_t)bh * Sq + q0 + wid*16 + lg;
        Lp[li]     = l0;
        Lp[li + 8] = l1;
    }
}

// ---------------------------------------------------------------------------
// Combine split-KV partials: O = (A+B)/(lA+lB), write fp16 hi/lo [bs][h*64+d]
// ---------------------------------------------------------------------------
__global__ __launch_bounds__(256) void combine_kv(
    const float* __restrict__ A, const float* __restrict__ B,
    const float* __restrict__ LA, const float* __restrict__ LB,
    __half* __restrict__ OH, __half* __restrict__ OL)
{
    int i = blockIdx.x * blockDim.x + threadIdx.x;
    int bs = i >> 8, c4 = i & 255;
    int h = c4 >> 4;
    int b = bs >> 11, s = bs & (Sq - 1);
    size_t li = ((size_t)(b*16 + h)) * Sq + s;
    float inv = 1.0f / (LA[li] + LB[li]);
    float4 a = ((const float4*)A)[i];
    float4 c = ((const float4*)B)[i];
    float x0 = (a.x + c.x) * inv, x1 = (a.y + c.y) * inv;
    float x2 = (a.z + c.z) * inv, x3 = (a.w + c.w) * inv;
    size_t o = (size_t)i * 4;
    store_hilo(OH, OL, o,     x0, x1);
    store_hilo(OH, OL, o + 2, x2, x3);
}

// ---------------------------------------------------------------------------
extern "C" void kernel_launch(void* const* d_in, const int* in_sizes, int n_in,
                              void* d_out, int out_size)
{
    (void)in_sizes; (void)n_in; (void)out_size;
    const float* q  = (const float*)d_in[0];
    const float* k  = (const float*)d_in[1];
    const float* v  = (const float*)d_in[2];
    const float* cs = (const float*)d_in[4];
    const float* sn = (const float*)d_in[5];
    const float* wq = (const float*)d_in[6];
    const float* bq = (const float*)d_in[7];
    const float* wk = (const float*)d_in[8];
    const float* bk = (const float*)d_in[9];
    const float* wv = (const float*)d_in[10];
    const float* bv = (const float*)d_in[11];
    const float* wo = (const float*)d_in[12];
    const float* bo = (const float*)d_in[13];
    const float* qn = (const float*)d_in[14];
    const float* kn = (const float*)d_in[15];
    float* out = (float*)d_out;

    __half *aH, *aL, *wH, *qh, *ql, *kh, *vh;
    float *pO0, *pO1, *pL0, *pL1;
    cudaGetSymbolAddress((void**)&aH, g_actH);
    cudaGetSymbolAddress((void**)&aL, g_actL);
    cudaGetSymbolAddress((void**)&wH, g_wH);
    cudaGetSymbolAddress((void**)&qh, g_Qh);
    cudaGetSymbolAddress((void**)&ql, g_Ql);
    cudaGetSymbolAddress((void**)&kh, g_Kh);
    cudaGetSymbolAddress((void**)&vh, g_Vh);
    cudaGetSymbolAddress((void**)&pO0, g_O0);
    cudaGetSymbolAddress((void**)&pO1, g_O1);
    cudaGetSymbolAddress((void**)&pL0, g_L0);
    cudaGetSymbolAddress((void**)&pL1, g_L1);

    const size_t actN = (size_t)Mq*Dq, wN = (size_t)Dq*Dq;
    const int actN4 = (int)(actN/4), wN4 = (int)(wN/4);
    const int gsm = 3 * STAGE_B;   // 73728
    cudaFuncSetAttribute(gemm_tc,  cudaFuncAttributeMaxDynamicSharedMemorySize, gsm);
    cudaFuncSetAttribute(gemm_qkv, cudaFuncAttributeMaxDynamicSharedMemorySize, gsm);
    cudaFuncSetAttribute(flash_attn_tc, cudaFuncAttributeMaxDynamicSharedMemorySize, ATT_SMEM);

    split_act<<<dim3(actN4/256, 3), 256>>>(q, k, v, aH, aL, actN4);
    conv_w<<<dim3(wN4/256, 4), 256>>>(wq, wk, wv, wo, wH, wN4);

    gemm_qkv<<<dim3(Dq/128, Mq/128, 3), 128, gsm>>>(
        aH, aL, wH, actN, wN, bq, bk, bv, qn, kn, cs, sn,
        qh, ql, kh, vh, Mq, Dq, Dq);

    flash_attn_tc<<<dim3(Sq/128, Bq*Hq, 2), 256, ATT_SMEM>>>(
        qh, ql, kh, vh, pO0, pO1, pL0, pL1);
    combine_kv<<<Mq*Dq/4/256, 256>>>(pO0, pO1, pL0, pL1, aH, aL);

    gemm_tc<<<dim3(Dq/128, Mq/128), 128, gsm>>>(aH, aL, wH + 3*wN, bo, out, Mq, Dq, Dq);
}

// round 17
// speedup vs baseline: 1.4540x; 1.0616x over previous
#include <cuda_runtime.h>
#include <cuda_fp16.h>
#include <math.h>
#include <stdint.h>

#define Bq  2
#define Sq  2048
#define Dq  1024
#define Hq  16
#define DKq 64
#define Mq  (Bq*Sq)   // 4096

// activation hi/lo: 3 slots (q,k,v inputs); slot 0 reused after attention
__device__ __half g_actH[(size_t)3*Mq*Dq];
__device__ __half g_actL[(size_t)3*Mq*Dq];
// weight fp16 (hi only): 4 slots (wq,wk,wv,wo)
__device__ __half g_wH[(size_t)4*Dq*Dq];
// head-major [b*16+h][s][64] fp16 attention operands
__device__ __half g_Qh[(size_t)Mq*Dq];
__device__ __half g_Ql[(size_t)Mq*Dq];
__device__ __half g_Kh[(size_t)Mq*Dq];
__device__ __half g_Vh[(size_t)Mq*Dq];
// split-KV partial O (fp32) and row sums l
__device__ float g_O0[(size_t)Mq*Dq];
__device__ float g_O1[(size_t)Mq*Dq];
__device__ float g_L0[(size_t)Bq*Hq*Sq];
__device__ float g_L1[(size_t)Bq*Hq*Sq];

// ---------------------------------------------------------------------------
// helpers
// ---------------------------------------------------------------------------
__device__ __forceinline__ uint32_t smem_u32(const void* p) {
    uint32_t a;
    asm("{ .reg .u64 t; cvta.to.shared.u64 t, %1; cvt.u32.u64 %0, t; }" : "=r"(a) : "l"(p));
    return a;
}
__device__ __forceinline__ void cpa16(uint32_t saddr, const void* g) {
    asm volatile("cp.async.ca.shared.global [%0], [%1], 16;" :: "r"(saddr), "l"(g));
}
__device__ __forceinline__ void ldsm4(uint32_t* r, uint32_t addr) {
    asm volatile("ldmatrix.sync.aligned.m8n8.x4.shared.b16 {%0,%1,%2,%3}, [%4];"
        : "=r"(r[0]), "=r"(r[1]), "=r"(r[2]), "=r"(r[3]) : "r"(addr));
}
__device__ __forceinline__ void ldsm4t(uint32_t* r, uint32_t addr) {
    asm volatile("ldmatrix.sync.aligned.m8n8.x4.trans.shared.b16 {%0,%1,%2,%3}, [%4];"
        : "=r"(r[0]), "=r"(r[1]), "=r"(r[2]), "=r"(r[3]) : "r"(addr));
}
__device__ __forceinline__ void mma_f16(float* c, const uint32_t* a, const uint32_t* b) {
    asm volatile("mma.sync.aligned.m16n8k16.row.col.f32.f16.f16.f32 "
        "{%0,%1,%2,%3}, {%4,%5,%6,%7}, {%8,%9}, {%0,%1,%2,%3};"
        : "+f"(c[0]), "+f"(c[1]), "+f"(c[2]), "+f"(c[3])
        : "r"(a[0]), "r"(a[1]), "r"(a[2]), "r"(a[3]), "r"(b[0]), "r"(b[1]));
}
__device__ __forceinline__ uint32_t pack_h2(float lo, float hi) {
    half2 t = __floats2half2_rn(lo, hi);
    return *(uint32_t*)&t;
}
__device__ __forceinline__ void store_hilo(__half* H, __half* L,
                                           size_t o, float x, float y) {
    __half hx = __float2half_rn(x);
    __half hy = __float2half_rn(y);
    *(half2*)(H + o) = __halves2half2(hx, hy);
    *(half2*)(L + o) = __halves2half2(
        __float2half_rn(x - __half2float(hx)),
        __float2half_rn(y - __half2float(hy)));
}

// ---------------------------------------------------------------------------
// fp32 -> fp16 hi/lo split (activations); grid.y selects tensor (3 slots).
// ---------------------------------------------------------------------------
__global__ __launch_bounds__(256) void split_act(
    const float* __restrict__ x0, const float* __restrict__ x1,
    const float* __restrict__ x2,
    __half* __restrict__ h, __half* __restrict__ l, int n4)
{
    const float* srcs[3] = { x0, x1, x2 };
    const float* x = srcs[blockIdx.y];
    size_t slot = (size_t)blockIdx.y * 2u * (size_t)n4;   // half2 units
    int i = blockIdx.x * blockDim.x + threadIdx.x;
    if (i >= n4) return;
    float4 v = ((const float4*)x)[i];
    __half h0 = __float2half_rn(v.x), h1 = __float2half_rn(v.y);
    __half h2 = __float2half_rn(v.z), h3 = __float2half_rn(v.w);
    ((half2*)h)[slot + 2*i]   = __halves2half2(h0, h1);
    ((half2*)h)[slot + 2*i+1] = __halves2half2(h2, h3);
    ((half2*)l)[slot + 2*i]   = __halves2half2(
        __float2half_rn(v.x - __half2float(h0)),
        __float2half_rn(v.y - __half2float(h1)));
    ((half2*)l)[slot + 2*i+1] = __halves2half2(
        __float2half_rn(v.z - __half2float(h2)),
        __float2half_rn(v.w - __half2float(h3)));
}

// fp32 -> fp16 plain convert (weights); grid.y selects one of 4 slots.
__global__ __launch_bounds__(256) void conv_w(
    const float* __restrict__ x0, const float* __restrict__ x1,
    const float* __restrict__ x2, const float* __restrict__ x3,
    __half* __restrict__ h, int n4)
{
    const float* srcs[4] = { x0, x1, x2, x3 };
    const float* x = srcs[blockIdx.y];
    size_t slot = (size_t)blockIdx.y * 2u * (size_t)n4;
    int i = blockIdx.x * blockDim.x + threadIdx.x;
    if (i >= n4) return;
    float4 v = ((const float4*)x)[i];
    ((half2*)h)[slot + 2*i]   = __floats2half2_rn(v.x, v.y);
    ((half2*)h)[slot + 2*i+1] = __floats2half2_rn(v.z, v.w);
}

// ---------------------------------------------------------------------------
// GEMM mainloop (fp16 2-term: acc += Ah*Wh + Al*Wh). 128x128 CTA tile,
// 4 warps (64x64), K-chunk 32, 3-stage cp.async pipeline.
// smem per stage (24KB): Ah | Al | Wh, each 128 rows x 64B.
// ---------------------------------------------------------------------------
#define TILE8K 8192
#define STAGE_B 24576
__device__ __forceinline__ void gemm_mainloop(
    const __half* const* srcs, uint32_t sbase, int tid,
    int wm, int wn, int lane, int K, float acc[4][8][4])
{
    const int nkc = K >> 5;
    const int lt  = lane >> 3;
    const int lr8 = lane & 7;

    #pragma unroll
    for (int st = 0; st < 2; st++) {
        const int kofs = st << 5;
        const uint32_t stb = sbase + st * STAGE_B;
        #pragma unroll
        for (int t = 0; t < 3; t++) {
            const char* s = (const char*)(srcs[t] + kofs);
            uint32_t db = stb + t * TILE8K;
            #pragma unroll
            for (int j = 0; j < 4; j++) {
                int idx = tid + j*128;
                int r = idx >> 2, c = idx & 3;
                cpa16(db + r*64 + ((c ^ ((r>>1)&3))<<4), s + (size_t)r*(K*2) + c*16);
            }
        }
        asm volatile("cp.async.commit_group;");
    }

    int buf = 0;
    for (int kc = 0; kc < nkc; kc++) {
        if (kc + 1 < nkc) asm volatile("cp.async.wait_group 1;");
        else              asm volatile("cp.async.wait_group 0;");
        __syncthreads();

        if (kc + 2 < nkc) {
            const int kofs = (kc + 2) << 5;
            int nb3 = buf + 2; if (nb3 >= 3) nb3 -= 3;
            const uint32_t stb = sbase + nb3 * STAGE_B;
            #pragma unroll
            for (int t = 0; t < 3; t++) {
                const char* s = (const char*)(srcs[t] + kofs);
                uint32_t db = stb + t * TILE8K;
                #pragma unroll
                for (int j = 0; j < 4; j++) {
                    int idx = tid + j*128;
                    int r = idx >> 2, c = idx & 3;
                    cpa16(db + r*64 + ((c ^ ((r>>1)&3))<<4), s + (size_t)r*(K*2) + c*16);
                }
            }
            asm volatile("cp.async.commit_group;");
        }

        const uint32_t abH = sbase + buf * STAGE_B;
        const uint32_t abL = abH + TILE8K;
        const uint32_t wbH = abH + 2 * TILE8K;

        #pragma unroll
        for (int ka = 0; ka < 2; ka++) {
            uint32_t aH[4][4], aL[4][4], bH[8][2];
            #pragma unroll
            for (int ma = 0; ma < 4; ma++) {
                int row = wm + ma*16 + ((lt & 1) << 3) + lr8;
                int ch  = (ka << 1) + (lt >> 1);
                uint32_t off = (uint32_t)(row*64 + ((ch ^ ((row>>1)&3)) << 4));
                ldsm4(aH[ma], abH + off);
                ldsm4(aL[ma], abL + off);
            }
            #pragma unroll
            for (int nb = 0; nb < 4; nb++) {
                int row = wn + nb*16 + ((lt >> 1) << 3) + lr8;
                int ch  = (ka << 1) + (lt & 1);
                uint32_t off = (uint32_t)(row*64 + ((ch ^ ((row>>1)&3)) << 4));
                uint32_t r[4];
                ldsm4(r, wbH + off);
                bH[2*nb][0]=r[0]; bH[2*nb][1]=r[1]; bH[2*nb+1][0]=r[2]; bH[2*nb+1][1]=r[3];
            }
            #pragma unroll
            for (int ma = 0; ma < 4; ma++)
                #pragma unroll
                for (int na = 0; na < 8; na++)
                    mma_f16(acc[ma][na], aH[ma], bH[na]);
            #pragma unroll
            for (int ma = 0; ma < 4; ma++)
                #pragma unroll
                for (int na = 0; na < 8; na++)
                    mma_f16(acc[ma][na], aL[ma], bH[na]);
        }
        buf++; if (buf >= 3) buf = 0;
    }
}

// ---------------------------------------------------------------------------
// Plain GEMM (out-projection): fp32 row-major C + bias.
// ---------------------------------------------------------------------------
__global__ __launch_bounds__(128) void gemm_tc(
    const __half* __restrict__ Ah, const __half* __restrict__ Al,
    const __half* __restrict__ Wh,
    const float* __restrict__ bias, float* __restrict__ C, int M, int N, int K)
{
    extern __shared__ __align__(1024) char sm[];
    const uint32_t sbase = smem_u32(sm);
    const int tid = threadIdx.x;
    const int wid = tid >> 5, lane = tid & 31;
    const int bm = blockIdx.y * 128, bn = blockIdx.x * 128;
    const int wm = (wid >> 1) * 64, wn = (wid & 1) * 64;

    const __half* srcs[3] = {
        Ah + (size_t)bm * K, Al + (size_t)bm * K, Wh + (size_t)bn * K };

    float acc[4][8][4] = {};
    gemm_mainloop(srcs, sbase, tid, wm, wn, lane, K, acc);

    #pragma unroll
    for (int ma = 0; ma < 4; ma++) {
        int r = bm + wm + ma*16 + (lane >> 2);
        #pragma unroll
        for (int na = 0; na < 8; na++) {
            int col = bn + wn + na*8 + (lane & 3)*2;
            float2 b2 = *(const float2*)(bias + col);
            float2 v0 = { acc[ma][na][0] + b2.x, acc[ma][na][1] + b2.y };
            float2 v1 = { acc[ma][na][2] + b2.x, acc[ma][na][3] + b2.y };
            *(float2*)(C + (size_t)r * N + col)       = v0;
            *(float2*)(C + (size_t)(r + 8) * N + col) = v1;
        }
    }
}

// ---------------------------------------------------------------------------
// Fused QKV GEMM: blockIdx.z = 0(Q)/1(K)/2(V). Epilogue: bias, then
// Q: norm+rope -> Qh/Ql;  K: norm+rope -> Kh only;  V: passthrough -> Vh.
// ---------------------------------------------------------------------------
__global__ __launch_bounds__(128) void gemm_qkv(
    const __half* __restrict__ Ah, const __half* __restrict__ Al,
    const __half* __restrict__ Wh, size_t strideA, size_t strideW,
    const float* __restrict__ bq, const float* __restrict__ bk,
    const float* __restrict__ bv,
    const float* __restrict__ qn, const float* __restrict__ kn,
    const float* __restrict__ cs, const float* __restrict__ sn,
    __half* __restrict__ Qh, __half* __restrict__ Ql,
    __half* __restrict__ Kh, __half* __restrict__ Vh,
    int M, int N, int K)
{
    extern __shared__ __align__(1024) char sm[];
    const uint32_t sbase = smem_u32(sm);
    const int tid = threadIdx.x;
    const int wid = tid >> 5, lane = tid & 31;
    const int bm = blockIdx.y * 128, bn = blockIdx.x * 128;
    const int wm = (wid >> 1) * 64, wn = (wid & 1) * 64;
    const int z = blockIdx.z;
    const size_t zA = (size_t)z * strideA, zW = (size_t)z * strideW;

    const __half* srcs[3] = {
        Ah + zA + (size_t)bm * K, Al + zA + (size_t)bm * K,
        Wh + zW + (size_t)bn * K };

    float acc[4][8][4] = {};
    gemm_mainloop(srcs, sbase, tid, wm, wn, lane, K, acc);

    const float* bias = (z == 0) ? bq : (z == 1) ? bk : bv;

    const int lg = lane >> 2, tg = lane & 3;
    const int h = (bn + wn) >> 6;

    float2 bb[8];
    #pragma unroll
    for (int na = 0; na < 8; na++)
        bb[na] = *(const float2*)(bias + bn + wn + na*8 + tg*2);

    float wt[8][2];
    if (z < 2) {
        const float* w = (z == 0) ? qn : kn;
        #pragma unroll
        for (int na = 0; na < 8; na++) {
            float2 w2 = *(const float2*)(w + na*8 + tg*2);
            wt[na][0] = w2.x; wt[na][1] = w2.y;
        }
    }

    #pragma unroll
    for (int ma = 0; ma < 4; ma++) {
        #pragma unroll
        for (int half_ = 0; half_ < 2; half_++) {
            int r = bm + wm + ma*16 + lg + half_*8;
            int b = r >> 11, s = r & (Sq - 1);
            size_t ob = (((size_t)(b*16 + h))*Sq + s)*64;

            float v[8][2];
            float ss = 0.f;
            #pragma unroll
            for (int na = 0; na < 8; na++) {
                v[na][0] = acc[ma][na][2*half_]   + bb[na].x;
                v[na][1] = acc[ma][na][2*half_+1] + bb[na].y;
                ss += v[na][0]*v[na][0] + v[na][1]*v[na][1];
            }

            if (z == 2) {
                #pragma unroll
                for (int na = 0; na < 8; na++)
                    *(half2*)(Vh + ob + na*8 + tg*2) =
                        __floats2half2_rn(v[na][0], v[na][1]);
            } else {
                ss += __shfl_xor_sync(0xffffffffu, ss, 1);
                ss += __shfl_xor_sync(0xffffffffu, ss, 2);
                float inv = rsqrtf(ss*(1.0f/64.0f) + 1e-6f);
                const float* crow = cs + (size_t)s*64;
                const float* srow = sn + (size_t)s*64;
                #pragma unroll
                for (int na = 0; na < 4; na++) {
                    int d = na*8 + tg*2;
                    float y0a = v[na][0]*inv*wt[na][0];
                    float y0b = v[na][1]*inv*wt[na][1];
                    float y1a = v[na+4][0]*inv*wt[na+4][0];
                    float y1b = v[na+4][1]*inv*wt[na+4][1];
                    float2 c0 = *(const float2*)(crow + d);
                    float2 s0 = *(const float2*)(srow + d);
                    float2 c1 = *(const float2*)(crow + d + 32);
                    float2 s1 = *(const float2*)(srow + d + 32);
                    float o0a = y0a*c0.x - y1a*s0.x;
                    float o0b = y0b*c0.y - y1b*s0.y;
                    float o1a = y1a*c1.x + y0a*s1.x;
                    float o1b = y1b*c1.y + y0b*s1.y;
                    if (z == 0) {
                        store_hilo(Qh, Ql, ob + d,      o0a, o0b);
                        store_hilo(Qh, Ql, ob + d + 32, o1a, o1b);
                    } else {
                        *(half2*)(Kh + ob + d)      = __floats2half2_rn(o0a, o0b);
                        *(half2*)(Kh + ob + d + 32) = __floats2half2_rn(o1a, o1b);
                    }
                }
            }
        }
    }
}

// ---------------------------------------------------------------------------
// Flash attention, causal, split-KV x2. fp16: Q hi/lo, K hi, P hi, V hi.
// Fixed-max softmax (S in [-8,8]); partials combine by addition.
// smem: Qh|Ql 32KB + 2 stages x (Kh|Vh) 16KB = 64KB.
// ---------------------------------------------------------------------------
#define ATT_SMEM 65536
__global__ __launch_bounds__(256, 2) void flash_attn_tc(
    const __half* __restrict__ Qh, const __half* __restrict__ Ql,
    const __half* __restrict__ Kh, const __half* __restrict__ Vh,
    float* __restrict__ O0p, float* __restrict__ O1p,
    float* __restrict__ L0p, float* __restrict__ L1p)
{
    extern __shared__ __align__(1024) char sm[];
    const uint32_t sQ = smem_u32(sm);
    const uint32_t sStage = sQ + 32768;
    const int tid = threadIdx.x, wid = tid >> 5, lane = tid & 31;
    const int qb = gridDim.x - 1 - blockIdx.x;
    const int bh = blockIdx.y;
    const int sId = blockIdx.z;
    const int q0 = qb * 128;
    const size_t hb = (size_t)bh * Sq * DKq;

    float* Op = sId ? O1p : O0p;
    float* Lp = sId ? L1p : L0p;

    const char* gQh = (const char*)(Qh + hb + (size_t)q0*64);
    const char* gQl = (const char*)(Ql + hb + (size_t)q0*64);
    const char* gKh = (const char*)(Kh + hb);
    const char* gVh = (const char*)(Vh + hb);

    const int kb0 = sId * (qb + 1);
    const int kbN = kb0 + (qb + 1);

    #pragma unroll
    for (int j = 0; j < 4; j++) {
        int i = tid + j*256;
        int r = i >> 3, c = i & 7;
        uint32_t so = (uint32_t)(r*128 + ((c ^ (r&7)) << 4));
        cpa16(sQ + so,         gQh + r*128 + c*16);
        cpa16(sQ + 16384 + so, gQl + r*128 + c*16);
    }
    {
        const char* gs[2] = { gKh, gVh };
        #pragma unroll
        for (int t = 0; t < 2; t++)
            #pragma unroll
            for (int j = 0; j < 2; j++) {
                int i = tid + j*256;
                int r = i >> 3, c = i & 7;
                uint32_t so = (uint32_t)(r*128 + ((c ^ (r&7)) << 4));
                cpa16(sStage + t*8192 + so, gs[t] + (size_t)(kb0*64 + r)*128 + c*16);
            }
    }
    asm volatile("cp.async.commit_group;");

    float o[8][4] = {};
    float S[8][4];
    float l0 = 0.f, l1 = 0.f;
    uint32_t qfh[4][4];

    const int lg = lane >> 2;
    const int tg = lane & 3;
    const int lrow = (((lane >> 3) & 1) << 3) + (lane & 7);
    const int lsel = lane >> 4;

    const float c1 = 0.125f * 1.4426950408889634f;
    const float c2 = 8.0f  * 1.4426950408889634f;

    for (int kb = kb0; kb < kbN; kb++) {
        const int ib = kb - kb0;
        if (kb + 1 < kbN) {
            const uint32_t stb = sStage + ((ib+1) & 1) * 16384;
            const int kvr = (kb+1) * 64;
            const char* gs[2] = { gKh, gVh };
            #pragma unroll
            for (int t = 0; t < 2; t++)
                #pragma unroll
                for (int j = 0; j < 2; j++) {
                    int i = tid + j*256;
                    int r = i >> 3, c = i & 7;
                    uint32_t so = (uint32_t)(r*128 + ((c ^ (r&7)) << 4));
                    cpa16(stb + t*8192 + so, gs[t] + (size_t)(kvr + r)*128 + c*16);
                }
            asm volatile("cp.async.commit_group;");
            asm volatile("cp.async.wait_group 1;");
        } else {
            asm volatile("cp.async.wait_group 0;");
        }
        __syncthreads();

        if (ib == 0) {
            #pragma unroll
            for (int ka = 0; ka < 4; ka++) {
                int r = wid*16 + lrow;
                int c = 2*ka + lsel;
                ldsm4(qfh[ka], sQ + (uint32_t)(r*128 + ((c ^ (r&7)) << 4)));
            }
        }

        const bool active = (kb*64 <= q0 + wid*16 + 15);
        if (active) {
            const uint32_t bK = sStage + (ib & 1) * 16384;
            #pragma unroll
            for (int n = 0; n < 8; n++)
                #pragma unroll
                for (int x = 0; x < 4; x++) S[n][x] = 0.f;

            #pragma unroll
            for (int ka = 0; ka < 4; ka++) {
                uint32_t qlw[4];
                {
                    int r = wid*16 + lrow;
                    int c = 2*ka + lsel;
                    ldsm4(qlw, sQ + 16384 + (uint32_t)(r*128 + ((c ^ (r&7)) << 4)));
                }
                #pragma unroll
                for (int n16 = 0; n16 < 4; n16++) {
                    int r = n16*16 + lrow;
                    int c = 2*ka + lsel;
                    uint32_t off = (uint32_t)(r*128 + ((c ^ (r&7)) << 4));
                    uint32_t kh4[4];
                    ldsm4(kh4, bK + off);
                    uint32_t bh0[2] = { kh4[0], kh4[2] }, bh1[2] = { kh4[1], kh4[3] };
                    mma_f16(S[2*n16],   qfh[ka], bh0);
                    mma_f16(S[2*n16],   qlw,     bh0);
                    mma_f16(S[2*n16+1], qfh[ka], bh1);
                    mma_f16(S[2*n16+1], qlw,     bh1);
                }
            }

            const int row0 = q0 + wid*16 + lg;
            const int row1 = row0 + 8;
            float sum0 = 0.f, sum1 = 0.f;
            if (kb >= 2*qb) {
                #pragma unroll
                for (int n = 0; n < 8; n++) {
                    int col0 = kb*64 + n*8 + tg*2;
                    float e0 = exp2f(fmaf(S[n][0], c1, -c2));
                    float e1 = exp2f(fmaf(S[n][1], c1, -c2));
                    float e2 = exp2f(fmaf(S[n][2], c1, -c2));
                    float e3 = exp2f(fmaf(S[n][3], c1, -c2));
                    if (col0     > row0) e0 = 0.f;
                    if (col0 + 1 > row0) e1 = 0.f;
                    if (col0     > row1) e2 = 0.f;
                    if (col0 + 1 > row1) e3 = 0.f;
                    S[n][0] = e0; S[n][1] = e1; S[n][2] = e2; S[n][3] = e3;
                    sum0 += e0 + e1;
                    sum1 += e2 + e3;
                }
            } else {
                #pragma unroll
                for (int n = 0; n < 8; n++) {
                    float e0 = exp2f(fmaf(S[n][0], c1, -c2));
                    float e1 = exp2f(fmaf(S[n][1], c1, -c2));
                    float e2 = exp2f(fmaf(S[n][2], c1, -c2));
                    float e3 = exp2f(fmaf(S[n][3], c1, -c2));
                    S[n][0] = e0; S[n][1] = e1; S[n][2] = e2; S[n][3] = e3;
                    sum0 += e0 + e1;
                    sum1 += e2 + e3;
                }
            }
            sum0 += __shfl_xor_sync(0xffffffffu, sum0, 1);
            sum0 += __shfl_xor_sync(0xffffffffu, sum0, 2);
            sum1 += __shfl_xor_sync(0xffffffffu, sum1, 1);
            sum1 += __shfl_xor_sync(0xffffffffu, sum1, 2);
            l0 += sum0;
            l1 += sum1;

            // ---- O += P V (P fp16 hi-only)
            // A-frag: a0=(r,k), a1=(r+8,k), a2=(r,k+8), a3=(r+8,k+8)
            // S[n]: {s0,s1}=row r, {s2,s3}=row r+8
            const uint32_t bV = bK + 8192;
            #pragma unroll
            for (int ka = 0; ka < 4; ka++) {
                uint32_t ah[4];
                ah[0] = pack_h2(S[2*ka][0],   S[2*ka][1]);
                ah[1] = pack_h2(S[2*ka][2],   S[2*ka][3]);
                ah[2] = pack_h2(S[2*ka+1][0], S[2*ka+1][1]);
                ah[3] = pack_h2(S[2*ka+1][2], S[2*ka+1][3]);
                #pragma unroll
                for (int ndp = 0; ndp < 4; ndp++) {
                    int r = ka*16 + lrow;
                    int c = 2*ndp + lsel;
                    uint32_t off = (uint32_t)(r*128 + ((c ^ (r&7)) << 4));
                    uint32_t vh4[4];
                    ldsm4t(vh4, bV + off);
                    uint32_t bh0[2] = { vh4[0], vh4[1] }, bh1[2] = { vh4[2], vh4[3] };
                    mma_f16(o[2*ndp],   ah, bh0);
                    mma_f16(o[2*ndp+1], ah, bh1);
                }
            }
        }
        __syncthreads();
    }

    const int b = bh >> 4, h = bh & 15;
    const int r0g = b*Sq + q0 + wid*16 + lg;
    size_t base0 = (size_t)r0g * Dq + h*64 + tg*2;
    size_t base1 = base0 + (size_t)8 * Dq;
    #pragma unroll
    for (int n = 0; n < 8; n++) {
        *(float2*)(Op + base0 + n*8) = make_float2(o[n][0], o[n][1]);
        *(float2*)(Op + base1 + n*8) = make_float2(o[n][2], o[n][3]);
    }
    if (tg == 0) {
        size_t li = (size_t)bh * Sq + q0 + wid*16 + lg;
        Lp[li]     = l0;
        Lp[li + 8] = l1;
    }
}

// ---------------------------------------------------------------------------
// Combine split-KV partials: O = (A+B)/(lA+lB), write fp16 hi/lo [bs][h*64+d]
// ---------------------------------------------------------------------------
__global__ __launch_bounds__(256) void combine_kv(
    const float* __restrict__ A, const float* __restrict__ B,
    const float* __restrict__ LA, const float* __restrict__ LB,
    __half* __restrict__ OH, __half* __restrict__ OL)
{
    int i = blockIdx.x * blockDim.x + threadIdx.x;
    int bs = i >> 8, c4 = i & 255;
    int h = c4 >> 4;
    int b = bs >> 11, s = bs & (Sq - 1);
    size_t li = ((size_t)(b*16 + h)) * Sq + s;
    float inv = 1.0f / (LA[li] + LB[li]);
    float4 a = ((const float4*)A)[i];
    float4 c = ((const float4*)B)[i];
    float x0 = (a.x + c.x) * inv, x1 = (a.y + c.y) * inv;
    float x2 = (a.z + c.z) * inv, x3 = (a.w + c.w) * inv;
    size_t o = (size_t)i * 4;
    store_hilo(OH, OL, o,     x0, x1);
    store_hilo(OH, OL, o + 2, x2, x3);
}

// ---------------------------------------------------------------------------
extern "C" void kernel_launch(void* const* d_in, const int* in_sizes, int n_in,
                              void* d_out, int out_size)
{
    (void)in_sizes; (void)n_in; (void)out_size;
    const float* q  = (const float*)d_in[0];
    const float* k  = (const float*)d_in[1];
    const float* v  = (const float*)d_in[2];
    const float* cs = (const float*)d_in[4];
    const float* sn = (const float*)d_in[5];
    const float* wq = (const float*)d_in[6];
    const float* bq = (const float*)d_in[7];
    const float* wk = (const float*)d_in[8];
    const float* bk = (const float*)d_in[9];
    const float* wv = (const float*)d_in[10];
    const float* bv = (const float*)d_in[11];
    const float* wo = (const float*)d_in[12];
    const float* bo = (const float*)d_in[13];
    const float* qn = (const float*)d_in[14];
    const float* kn = (const float*)d_in[15];
    float* out = (float*)d_out;

    __half *aH, *aL, *wH, *qh, *ql, *kh, *vh;
    float *pO0, *pO1, *pL0, *pL1;
    cudaGetSymbolAddress((void**)&aH, g_actH);
    cudaGetSymbolAddress((void**)&aL, g_actL);
    cudaGetSymbolAddress((void**)&wH, g_wH);
    cudaGetSymbolAddress((void**)&qh, g_Qh);
    cudaGetSymbolAddress((void**)&ql, g_Ql);
    cudaGetSymbolAddress((void**)&kh, g_Kh);
    cudaGetSymbolAddress((void**)&vh, g_Vh);
    cudaGetSymbolAddress((void**)&pO0, g_O0);
    cudaGetSymbolAddress((void**)&pO1, g_O1);
    cudaGetSymbolAddress((void**)&pL0, g_L0);
    cudaGetSymbolAddress((void**)&pL1, g_L1);

    const size_t actN = (size_t)Mq*Dq, wN = (size_t)Dq*Dq;
    const int actN4 = (int)(actN/4), wN4 = (int)(wN/4);
    const int gsm = 3 * STAGE_B;   // 73728
    cudaFuncSetAttribute(gemm_tc,  cudaFuncAttributeMaxDynamicSharedMemorySize, gsm);
    cudaFuncSetAttribute(gemm_qkv, cudaFuncAttributeMaxDynamicSharedMemorySize, gsm);
    cudaFuncSetAttribute(flash_attn_tc, cudaFuncAttributeMaxDynamicSharedMemorySize, ATT_SMEM);

    split_act<<<dim3(actN4/256, 3), 256>>>(q, k, v, aH, aL, actN4);
    conv_w<<<dim3(wN4/256, 4), 256>>>(wq, wk, wv, wo, wH, wN4);

    gemm_qkv<<<dim3(Dq/128, Mq/128, 3), 128, gsm>>>(
        aH, aL, wH, actN, wN, bq, bk, bv, qn, kn, cs, sn,
        qh, ql, kh, vh, Mq, Dq, Dq);

    flash_attn_tc<<<dim3(Sq/128, Bq*Hq, 2), 256, ATT_SMEM>>>(
        qh, ql, kh, vh, pO0, pO1, pL0, pL1);
    combine_kv<<<Mq*Dq/4/256, 256>>>(pO0, pO1, pL0, pL1, aH, aL);

    gemm_tc<<<dim3(Dq/128, Mq/128), 128, gsm>>>(aH, aL, wH + 3*wN, bo, out, Mq, Dq, Dq);
}